// round 9
// baseline (speedup 1.0000x reference)
#include <cuda_runtime.h>
#include <cuda_bf16.h>
#include <math.h>
#include <stdint.h>

// Problem constants
#define BB    8
#define NSEQ  1024
#define DDIM  1024
#define NH    16
#define DHEAD 64
#define MROWS (BB * NSEQ)   // 8192

// ============================ PTX helpers ====================================
__device__ __forceinline__ uint32_t smem_u32(const void* p) {
    uint32_t a;
    asm("{ .reg .u64 t; cvta.to.shared.u64 t, %1; cvt.u32.u64 %0, t; }" : "=r"(a) : "l"(p));
    return a;
}
__device__ __forceinline__ void cp16(uint32_t d, const void* s) {
    asm volatile("cp.async.cg.shared.global [%0], [%1], 16;" :: "r"(d), "l"(s) : "memory");
}
#define CP_COMMIT() asm volatile("cp.async.commit_group;" ::: "memory")
#define CP_WAIT(n)  asm volatile("cp.async.wait_group %0;" :: "n"(n) : "memory")

__device__ __forceinline__ void ldsm4(uint32_t* r, uint32_t a) {
    asm volatile("ldmatrix.sync.aligned.m8n8.x4.shared.b16 {%0,%1,%2,%3}, [%4];"
        : "=r"(r[0]), "=r"(r[1]), "=r"(r[2]), "=r"(r[3]) : "r"(a));
}
__device__ __forceinline__ void ldsm4t(uint32_t* r, uint32_t a) {
    asm volatile("ldmatrix.sync.aligned.m8n8.x4.trans.shared.b16 {%0,%1,%2,%3}, [%4];"
        : "=r"(r[0]), "=r"(r[1]), "=r"(r[2]), "=r"(r[3]) : "r"(a));
}
__device__ __forceinline__ void mma16816(float* c, const uint32_t* a, const uint32_t* b) {
    asm volatile("mma.sync.aligned.m16n8k16.row.col.f32.bf16.bf16.f32 "
        "{%0,%1,%2,%3}, {%4,%5,%6,%7}, {%8,%9}, {%0,%1,%2,%3};"
        : "+f"(c[0]), "+f"(c[1]), "+f"(c[2]), "+f"(c[3])
        : "r"(a[0]), "r"(a[1]), "r"(a[2]), "r"(a[3]), "r"(b[0]), "r"(b[1]));
}
__device__ __forceinline__ void hi_lo_pack(float x, float y, uint32_t& h, uint32_t& l) {
    __nv_bfloat16 hx = __float2bfloat16(x), hy = __float2bfloat16(y);
    __nv_bfloat16 lx = __float2bfloat16(x - __bfloat162float(hx));
    __nv_bfloat16 ly = __float2bfloat16(y - __bfloat162float(hy));
    __nv_bfloat162 hv(hx, hy), lv(lx, ly);
    h = *(uint32_t*)&hv; l = *(uint32_t*)&lv;
}

// ============================ scratch buffers ================================
__device__ float g_ao[(size_t)MROWS * DDIM];
__device__ float g_h1[(size_t)MROWS * DDIM];
__device__ float g_t [(size_t)MROWS * DDIM];

__device__ __align__(1024) __nv_bfloat16 g_axh[(size_t)MROWS * DDIM];
__device__ __align__(1024) __nv_bfloat16 g_axl[(size_t)MROWS * DDIM];
__device__ __align__(1024) __nv_bfloat16 g_ayh[(size_t)MROWS * DDIM];
__device__ __align__(1024) __nv_bfloat16 g_ayl[(size_t)MROWS * DDIM];
__device__ __align__(1024) __nv_bfloat16 g_wth[4][(size_t)DDIM * DDIM];
__device__ __align__(1024) __nv_bfloat16 g_wtl[4][(size_t)DDIM * DDIM];
__device__ __align__(1024) __nv_bfloat16 g_qh[(size_t)MROWS * DDIM];
__device__ __align__(1024) __nv_bfloat16 g_ql[(size_t)MROWS * DDIM];
__device__ __align__(1024) __nv_bfloat16 g_kh[(size_t)MROWS * DDIM];
__device__ __align__(1024) __nv_bfloat16 g_kl[(size_t)MROWS * DDIM];
__device__ __align__(1024) __nv_bfloat16 g_vh[(size_t)MROWS * DDIM];
__device__ __align__(1024) __nv_bfloat16 g_vl[(size_t)MROWS * DDIM];

// ============================ split / transpose ==============================
// z=0: split x ; z=1: split y
__global__ __launch_bounds__(256)
void split2_kernel(const float* __restrict__ in0, const float* __restrict__ in1,
                   __nv_bfloat16* __restrict__ hi0, __nv_bfloat16* __restrict__ lo0,
                   __nv_bfloat16* __restrict__ hi1, __nv_bfloat16* __restrict__ lo1)
{
    const float* in = blockIdx.z ? in1 : in0;
    __nv_bfloat16* hi = blockIdx.z ? hi1 : hi0;
    __nv_bfloat16* lo = blockIdx.z ? lo1 : lo0;
    int i = blockIdx.x * 256 + threadIdx.x;
    float4 v = ((const float4*)in)[i];
    uint32_t h01, l01, h23, l23;
    hi_lo_pack(v.x, v.y, h01, l01);
    hi_lo_pack(v.z, v.w, h23, l23);
    uint2 hw, lw;
    hw.x = h01; hw.y = h23; lw.x = l01; lw.y = l23;
    ((uint2*)hi)[i] = hw;
    ((uint2*)lo)[i] = lw;
}

// 4 weights transposed+split in one launch (z selects weight)
__global__ __launch_bounds__(256)
void tsplit4_kernel(const float* __restrict__ W0, const float* __restrict__ W1,
                    const float* __restrict__ W2, const float* __restrict__ W3,
                    __nv_bfloat16* __restrict__ thb, __nv_bfloat16* __restrict__ tlb)
{
    const int w = blockIdx.z;
    const float* W = (w == 0) ? W0 : (w == 1) ? W1 : (w == 2) ? W2 : W3;
    __nv_bfloat16* th = thb + (size_t)w * DDIM * DDIM;
    __nv_bfloat16* tl = tlb + (size_t)w * DDIM * DDIM;

    __shared__ float t[32][33];
    const int tx = threadIdx.x & 31;
    const int ty = threadIdx.x >> 5;
    const int kb = blockIdx.y * 32;
    const int nb = blockIdx.x * 32;
#pragma unroll
    for (int i = 0; i < 4; i++) {
        int kk = ty + i * 8;
        t[kk][tx] = W[(size_t)(kb + kk) * DDIM + nb + tx];
    }
    __syncthreads();
#pragma unroll
    for (int i = 0; i < 4; i++) {
        int nn = ty + i * 8;
        float v = t[tx][nn];
        __nv_bfloat16 h = __float2bfloat16(v);
        __nv_bfloat16 l = __float2bfloat16(v - __bfloat162float(h));
        size_t o = (size_t)(nb + nn) * DDIM + kb + tx;
        th[o] = h; tl[o] = l;
    }
}

// ============================ HMMA GEMM (bf16 split, fp32 acc) ===============
// BM=256, BN=256, BK=32, 512 threads, warp tile 64x64 (4m x 4n warps), 2 stages.
// EPI 0: C = A@W + b. EPI 1: C = relu(A@W+b)+res. EPI 2: bf16 hi/lo split out.
#define G_SST   80                        // smem row stride bytes (40 bf16)
#define G_T     (256 * G_SST)             // 20480 per tile
#define G_STAGE (4 * G_T)                 // 81920 : Ah,Al,Bh,Bl
#define GSMEM   (2 * G_STAGE)             // 163840

template <int EPI>
__global__ __launch_bounds__(512)
void gemm_mma(const __nv_bfloat16* __restrict__ Ah_, const __nv_bfloat16* __restrict__ Al_,
              const __nv_bfloat16* __restrict__ Bh_, const __nv_bfloat16* __restrict__ Bl_,
              const float* __restrict__ bias, const float* __restrict__ res,
              float* __restrict__ C,
              __nv_bfloat16* __restrict__ Ch, __nv_bfloat16* __restrict__ Cl)
{
    extern __shared__ __align__(128) char gsm[];
    const uint32_t sb = smem_u32(gsm);
    const int tid = threadIdx.x, lid = tid & 31, wid = tid >> 5;
    const int wm = (wid & 3) * 64, wn = (wid >> 2) * 64;
    const int bm = blockIdx.y * 256, bn = blockIdx.x * 256;

    const uint32_t aoff = (uint32_t)(wm + (lid & 15)) * G_SST + (((lid >> 4) & 1) * 16);
    const uint32_t boff = (uint32_t)(((lid >> 4) & 1) * 8 + (lid & 7)) * G_SST
                        + (((lid >> 3) & 1) * 16);

    float acc[4][8][4];
#pragma unroll
    for (int i = 0; i < 4; i++)
#pragma unroll
        for (int j = 0; j < 8; j++)
#pragma unroll
            for (int e = 0; e < 4; e++) acc[i][j][e] = 0.0f;

    // per-stage: each tensor 256 rows x 4 segs(16B) = 1024 cp16; thread does 2/tensor
    auto LOAD = [&](int stg, int k0) {
        const uint32_t s = sb + (uint32_t)stg * G_STAGE;
#pragma unroll
        for (int t = 0; t < 2; t++) {
            int idx = tid + t * 512;
            int r = idx >> 2, sg = idx & 3;
            uint32_t so = (uint32_t)r * G_SST + sg * 16;
            size_t goA = (size_t)(bm + r) * DDIM + k0 + sg * 8;
            size_t goB = (size_t)(bn + r) * DDIM + k0 + sg * 8;
            cp16(s + so,             Ah_ + goA);
            cp16(s + G_T + so,       Al_ + goA);
            cp16(s + 2 * G_T + so,   Bh_ + goB);
            cp16(s + 3 * G_T + so,   Bl_ + goB);
        }
    };

    LOAD(0, 0);
    CP_COMMIT();

    for (int c = 0; c < 32; c++) {
        if (c + 1 < 32) { LOAD((c + 1) & 1, (c + 1) * 32); CP_COMMIT(); CP_WAIT(1); }
        else            { CP_WAIT(0); }
        __syncthreads();
        const uint32_t st = sb + (uint32_t)(c & 1) * G_STAGE;

#pragma unroll
        for (int s = 0; s < 2; s++) {
            const uint32_t ks = s * 32;
            uint32_t AH[4][4], AL[4][4];
#pragma unroll
            for (int i = 0; i < 4; i++) {
                ldsm4(AH[i], st + aoff + (uint32_t)(i * 16) * G_SST + ks);
                ldsm4(AL[i], st + G_T + aoff + (uint32_t)(i * 16) * G_SST + ks);
            }
#pragma unroll
            for (int g = 0; g < 4; g++) {
                uint32_t BH[4], BL[4];
                const uint32_t ba = st + 2 * G_T
                                  + (uint32_t)(wn + g * 16) * G_SST + boff + ks;
                ldsm4(BH, ba);
                ldsm4(BL, ba + G_T);
#pragma unroll
                for (int i = 0; i < 4; i++) {
                    mma16816(acc[i][2 * g],     AH[i], &BH[0]);
                    mma16816(acc[i][2 * g + 1], AH[i], &BH[2]);
                }
#pragma unroll
                for (int i = 0; i < 4; i++) {
                    mma16816(acc[i][2 * g],     AL[i], &BH[0]);
                    mma16816(acc[i][2 * g + 1], AL[i], &BH[2]);
                }
#pragma unroll
                for (int i = 0; i < 4; i++) {
                    mma16816(acc[i][2 * g],     AH[i], &BL[0]);
                    mma16816(acc[i][2 * g + 1], AH[i], &BL[2]);
                }
            }
        }
        __syncthreads();
    }

    // epilogue
    const int gr = lid >> 2, gc = (lid & 3) * 2;
#pragma unroll
    for (int i = 0; i < 4; i++) {
        const int r0 = bm + wm + i * 16 + gr;
        const int r1 = r0 + 8;
#pragma unroll
        for (int j = 0; j < 8; j++) {
            const int col = bn + wn + j * 8 + gc;
            const float bx = bias[col], by = bias[col + 1];
            float v0 = acc[i][j][0] + bx, v1 = acc[i][j][1] + by;
            float v2 = acc[i][j][2] + bx, v3 = acc[i][j][3] + by;
            if (EPI == 2) {
                uint32_t h01, l01, h23, l23;
                hi_lo_pack(v0, v1, h01, l01);
                hi_lo_pack(v2, v3, h23, l23);
                *(uint32_t*)(Ch + (size_t)r0 * DDIM + col) = h01;
                *(uint32_t*)(Cl + (size_t)r0 * DDIM + col) = l01;
                *(uint32_t*)(Ch + (size_t)r1 * DDIM + col) = h23;
                *(uint32_t*)(Cl + (size_t)r1 * DDIM + col) = l23;
            } else {
                if (EPI == 1) {
                    const float* rp0 = res + (size_t)r0 * DDIM + col;
                    const float* rp1 = res + (size_t)r1 * DDIM + col;
                    v0 = fmaxf(v0, 0.0f) + rp0[0];
                    v1 = fmaxf(v1, 0.0f) + rp0[1];
                    v2 = fmaxf(v2, 0.0f) + rp1[0];
                    v3 = fmaxf(v3, 0.0f) + rp1[1];
                }
                *(float2*)(C + (size_t)r0 * DDIM + col) = make_float2(v0, v1);
                *(float2*)(C + (size_t)r1 * DDIM + col) = make_float2(v2, v3);
            }
        }
    }
}

// ============================ HMMA flash attention ===========================
// CTA: 256 q-rows of one (b,h), 512 threads (16 warps x 16 rows).
// K/V chunks of 128, 2-stage.
#define AST_B   144
#define ATILE_B (128 * AST_B)              // 18432
#define AQT_B   (256 * AST_B)              // 36864
#define ASMEM   (2 * AQT_B + 8 * ATILE_B)  // 221184

__global__ __launch_bounds__(512, 1)
void attn_mma(const __nv_bfloat16* __restrict__ Qh_g, const __nv_bfloat16* __restrict__ Ql_g,
              const __nv_bfloat16* __restrict__ Kh_g, const __nv_bfloat16* __restrict__ Kl_g,
              const __nv_bfloat16* __restrict__ Vh_g, const __nv_bfloat16* __restrict__ Vl_g,
              float* __restrict__ O)
{
    extern __shared__ __align__(128) char asm_[];
    const uint32_t sb = smem_u32(asm_);
    const int tid = threadIdx.x, lid = tid & 31, wid = tid >> 5;
    const int bh = blockIdx.y, b = bh >> 4, h = bh & 15;
    const int q0 = blockIdx.x * 256;

    const size_t qbase = (size_t)(b * NSEQ + q0) * DDIM + h * DHEAD;
    const size_t kbase = (size_t)(b * NSEQ) * DDIM + h * DHEAD;

    const uint32_t sQh = sb, sQl = sb + AQT_B;
    const uint32_t kv0 = sb + 2 * AQT_B;
    const uint32_t aoff = (uint32_t)(16 * wid + (lid & 15)) * AST_B + ((lid >> 4) & 1) * 16;
    const uint32_t boff = (uint32_t)(((lid >> 4) & 1) * 8 + (lid & 7)) * AST_B
                        + ((lid >> 3) & 1) * 16;
    const uint32_t voff = (uint32_t)(lid & 15) * AST_B + ((lid >> 4) & 1) * 16;

    auto loadKV = [&](int kt, int st) {
        const uint32_t base = kv0 + (uint32_t)st * (4 * ATILE_B);
        const size_t gk = kbase + (size_t)(kt * 128) * DDIM;
        for (int i = tid; i < 1024; i += 512) {
            int r = i >> 3, sg = i & 7;
            uint32_t so = (uint32_t)r * AST_B + sg * 16;
            size_t go = gk + (size_t)r * DDIM + sg * 8;
            cp16(base + so,               Kh_g + go);
            cp16(base + ATILE_B + so,     Kl_g + go);
            cp16(base + 2 * ATILE_B + so, Vh_g + go);
            cp16(base + 3 * ATILE_B + so, Vl_g + go);
        }
    };

    // prologue: Q (256 rows) + KV0, KV1
    for (int i = tid; i < 2048; i += 512) {
        int r = i >> 3, sg = i & 7;
        uint32_t so = (uint32_t)r * AST_B + sg * 16;
        size_t go = qbase + (size_t)r * DDIM + sg * 8;
        cp16(sQh + so, Qh_g + go);
        cp16(sQl + so, Ql_g + go);
    }
    loadKV(0, 0);
    CP_COMMIT();
    loadKV(1, 1);
    CP_COMMIT();
    CP_WAIT(1);
    __syncthreads();

    float m0 = -1e30f, m1 = -1e30f, l0v = 0.0f, l1v = 0.0f;
    float ov[8][4];
#pragma unroll
    for (int j = 0; j < 8; j++)
#pragma unroll
        for (int e = 0; e < 4; e++) ov[j][e] = 0.0f;

    for (int kt = 0; kt < 8; kt++) {
        const uint32_t kvb = kv0 + (uint32_t)(kt & 1) * (4 * ATILE_B);

        float sacc[16][4];
#pragma unroll
        for (int t = 0; t < 16; t++)
#pragma unroll
            for (int e = 0; e < 4; e++) sacc[t][e] = 0.0f;

#pragma unroll
        for (int kk = 0; kk < 4; kk++) {
            uint32_t QH[4], QL[4];
            ldsm4(QH, sQh + aoff + kk * 32);
            ldsm4(QL, sQl + aoff + kk * 32);
#pragma unroll
            for (int n = 0; n < 8; n++) {
                uint32_t KB[4];
                ldsm4(KB, kvb + boff + (uint32_t)n * (16 * AST_B) + kk * 32);
                mma16816(sacc[2 * n],     QH, &KB[0]);
                mma16816(sacc[2 * n + 1], QH, &KB[2]);
                mma16816(sacc[2 * n],     QL, &KB[0]);
                mma16816(sacc[2 * n + 1], QL, &KB[2]);
                ldsm4(KB, kvb + ATILE_B + boff + (uint32_t)n * (16 * AST_B) + kk * 32);
                mma16816(sacc[2 * n],     QH, &KB[0]);
                mma16816(sacc[2 * n + 1], QH, &KB[2]);
            }
        }

        const float scale = 0.03125f;
        float mx0 = -1e30f, mx1 = -1e30f;
#pragma unroll
        for (int t = 0; t < 16; t++) {
            sacc[t][0] *= scale; sacc[t][1] *= scale;
            sacc[t][2] *= scale; sacc[t][3] *= scale;
            mx0 = fmaxf(mx0, fmaxf(sacc[t][0], sacc[t][1]));
            mx1 = fmaxf(mx1, fmaxf(sacc[t][2], sacc[t][3]));
        }
        mx0 = fmaxf(mx0, __shfl_xor_sync(0xffffffffu, mx0, 1));
        mx0 = fmaxf(mx0, __shfl_xor_sync(0xffffffffu, mx0, 2));
        mx1 = fmaxf(mx1, __shfl_xor_sync(0xffffffffu, mx1, 1));
        mx1 = fmaxf(mx1, __shfl_xor_sync(0xffffffffu, mx1, 2));
        const float mn0 = fmaxf(m0, mx0), mn1 = fmaxf(m1, mx1);
        const float a0 = __expf(m0 - mn0), a1 = __expf(m1 - mn1);
        float rs0 = 0.0f, rs1 = 0.0f;
#pragma unroll
        for (int t = 0; t < 16; t++) {
            float e0 = __expf(sacc[t][0] - mn0);
            float e1 = __expf(sacc[t][1] - mn0);
            float e2 = __expf(sacc[t][2] - mn1);
            float e3 = __expf(sacc[t][3] - mn1);
            sacc[t][0] = e0; sacc[t][1] = e1; sacc[t][2] = e2; sacc[t][3] = e3;
            rs0 += e0 + e1; rs1 += e2 + e3;
        }
        rs0 += __shfl_xor_sync(0xffffffffu, rs0, 1);
        rs0 += __shfl_xor_sync(0xffffffffu, rs0, 2);
        rs1 += __shfl_xor_sync(0xffffffffu, rs1, 1);
        rs1 += __shfl_xor_sync(0xffffffffu, rs1, 2);
        l0v = l0v * a0 + rs0;
        l1v = l1v * a1 + rs1;
        m0 = mn0; m1 = mn1;
#pragma unroll
        for (int j = 0; j < 8; j++) {
            ov[j][0] *= a0; ov[j][1] *= a0;
            ov[j][2] *= a1; ov[j][3] *= a1;
        }

        const uint32_t sVh = kvb + 2 * ATILE_B, sVl = kvb + 3 * ATILE_B;
#pragma unroll
        for (int t = 0; t < 8; t++) {
            uint32_t aPh[4], aPl[4];
            hi_lo_pack(sacc[2 * t][0],     sacc[2 * t][1],     aPh[0], aPl[0]);
            hi_lo_pack(sacc[2 * t][2],     sacc[2 * t][3],     aPh[1], aPl[1]);
            hi_lo_pack(sacc[2 * t + 1][0], sacc[2 * t + 1][1], aPh[2], aPl[2]);
            hi_lo_pack(sacc[2 * t + 1][2], sacc[2 * t + 1][3], aPh[3], aPl[3]);
#pragma unroll
            for (int nv = 0; nv < 4; nv++) {
                uint32_t VB[4];
                ldsm4t(VB, sVh + voff + (uint32_t)t * (16 * AST_B) + nv * 32);
                mma16816(ov[2 * nv],     aPh, &VB[0]);
                mma16816(ov[2 * nv + 1], aPh, &VB[2]);
                mma16816(ov[2 * nv],     aPl, &VB[0]);
                mma16816(ov[2 * nv + 1], aPl, &VB[2]);
                ldsm4t(VB, sVl + voff + (uint32_t)t * (16 * AST_B) + nv * 32);
                mma16816(ov[2 * nv],     aPh, &VB[0]);
                mma16816(ov[2 * nv + 1], aPh, &VB[2]);
            }
        }

        __syncthreads();
        if (kt + 2 < 8) {
            loadKV(kt + 2, kt & 1);
            CP_COMMIT();
            CP_WAIT(1);
            __syncthreads();
        } else if (kt + 1 < 8) {
            CP_WAIT(0);
            __syncthreads();
        }
    }

    const float inv0 = 1.0f / l0v, inv1 = 1.0f / l1v;
    const int gr = lid >> 2, gc = (lid & 3) * 2;
    float* op0 = O + (size_t)(b * NSEQ + q0 + 16 * wid + gr) * DDIM + h * DHEAD;
    float* op1 = op0 + 8 * DDIM;
#pragma unroll
    for (int j = 0; j < 8; j++) {
        *(float2*)(op0 + j * 8 + gc) = make_float2(ov[j][0] * inv0, ov[j][1] * inv0);
        *(float2*)(op1 + j * 8 + gc) = make_float2(ov[j][2] * inv1, ov[j][3] * inv1);
    }
}

// ============================ LayerNorm (+ optional bf16 split out) ==========
__global__ __launch_bounds__(256)
void ln_kernel(const float* __restrict__ A, const float* __restrict__ R,
               const float* __restrict__ gamma, const float* __restrict__ beta,
               float* __restrict__ out,
               __nv_bfloat16* __restrict__ hi, __nv_bfloat16* __restrict__ lo)
{
    const int row = blockIdx.x;
    const int tid = threadIdx.x;
    const size_t base = (size_t)row * DDIM + tid * 4;

    float4 v = *(const float4*)(A + base);
    if (R != nullptr) {
        float4 r = *(const float4*)(R + base);
        v.x += r.x; v.y += r.y; v.z += r.z; v.w += r.w;
    }

    __shared__ float red1[8];
    __shared__ float red2[8];

    float s = v.x + v.y + v.z + v.w;
#pragma unroll
    for (int off = 16; off > 0; off >>= 1) s += __shfl_xor_sync(0xffffffffu, s, off);
    if ((tid & 31) == 0) red1[tid >> 5] = s;
    __syncthreads();
    float tot = 0.0f;
#pragma unroll
    for (int k = 0; k < 8; k++) tot += red1[k];
    float mean = tot * (1.0f / 1024.0f);

    float d0 = v.x - mean, d1 = v.y - mean, d2 = v.z - mean, d3 = v.w - mean;
    float sq = d0 * d0 + d1 * d1 + d2 * d2 + d3 * d3;
#pragma unroll
    for (int off = 16; off > 0; off >>= 1) sq += __shfl_xor_sync(0xffffffffu, sq, off);
    if ((tid & 31) == 0) red2[tid >> 5] = sq;
    __syncthreads();
    float vtot = 0.0f;
#pragma unroll
    for (int k = 0; k < 8; k++) vtot += red2[k];
    float rstd = rsqrtf(vtot * (1.0f / 1024.0f) + 1e-6f);

    float4 g4 = *(const float4*)(gamma + tid * 4);
    float4 b4 = *(const float4*)(beta  + tid * 4);
    float4 o4 = make_float4(d0 * rstd * g4.x + b4.x,
                            d1 * rstd * g4.y + b4.y,
                            d2 * rstd * g4.z + b4.z,
                            d3 * rstd * g4.w + b4.w);
    *(float4*)(out + base) = o4;

    if (hi != nullptr) {
        uint32_t h01, l01, h23, l23;
        hi_lo_pack(o4.x, o4.y, h01, l01);
        hi_lo_pack(o4.z, o4.w, h23, l23);
        uint2 hw, lw;
        hw.x = h01; hw.y = h23;
        lw.x = l01; lw.y = l23;
        *(uint2*)(hi + base) = hw;
        *(uint2*)(lo + base) = lw;
    }
}

// ============================ host launch ====================================
extern "C" void kernel_launch(void* const* d_in, const int* in_sizes, int n_in,
                              void* d_out, int out_size)
{
    (void)in_sizes; (void)n_in; (void)out_size;
    const float* x  = (const float*)d_in[0];
    const float* y  = (const float*)d_in[1];
    const float* Wq = (const float*)d_in[2];
    const float* bq = (const float*)d_in[3];
    const float* Wk = (const float*)d_in[4];
    const float* bk = (const float*)d_in[5];
    const float* Wv = (const float*)d_in[6];
    const float* bv = (const float*)d_in[7];
    const float* Wf = (const float*)d_in[8];
    const float* bf = (const float*)d_in[9];
    const float* g1 = (const float*)d_in[10];
    const float* b1 = (const float*)d_in[11];
    const float* g2 = (const float*)d_in[12];
    const float* b2 = (const float*)d_in[13];
    float* out = (float*)d_out;

    float *pao, *ph1, *pt;
    cudaGetSymbolAddress((void**)&pao, g_ao);
    cudaGetSymbolAddress((void**)&ph1, g_h1);
    cudaGetSymbolAddress((void**)&pt,  g_t);

    void *paxh, *paxl, *payh, *payl, *pwth, *pwtl;
    void *pqh, *pql, *pkh, *pkl, *pvh, *pvl;
    cudaGetSymbolAddress(&paxh, g_axh);
    cudaGetSymbolAddress(&paxl, g_axl);
    cudaGetSymbolAddress(&payh, g_ayh);
    cudaGetSymbolAddress(&payl, g_ayl);
    cudaGetSymbolAddress(&pwth, g_wth);
    cudaGetSymbolAddress(&pwtl, g_wtl);
    cudaGetSymbolAddress(&pqh, g_qh);
    cudaGetSymbolAddress(&pql, g_ql);
    cudaGetSymbolAddress(&pkh, g_kh);
    cudaGetSymbolAddress(&pkl, g_kl);
    cudaGetSymbolAddress(&pvh, g_vh);
    cudaGetSymbolAddress(&pvl, g_vl);

    __nv_bfloat16* axh = (__nv_bfloat16*)paxh;
    __nv_bfloat16* axl = (__nv_bfloat16*)paxl;
    __nv_bfloat16* ayh = (__nv_bfloat16*)payh;
    __nv_bfloat16* ayl = (__nv_bfloat16*)payl;
    __nv_bfloat16* wth = (__nv_bfloat16*)pwth;
    __nv_bfloat16* wtl = (__nv_bfloat16*)pwtl;
    __nv_bfloat16* qh = (__nv_bfloat16*)pqh;
    __nv_bfloat16* ql = (__nv_bfloat16*)pql;
    __nv_bfloat16* kh = (__nv_bfloat16*)pkh;
    __nv_bfloat16* kl = (__nv_bfloat16*)pkl;
    __nv_bfloat16* vh = (__nv_bfloat16*)pvh;
    __nv_bfloat16* vl = (__nv_bfloat16*)pvl;
    const size_t WSZ = (size_t)DDIM * DDIM;

    cudaFuncSetAttribute(gemm_mma<0>, cudaFuncAttributeMaxDynamicSharedMemorySize, GSMEM);
    cudaFuncSetAttribute(gemm_mma<1>, cudaFuncAttributeMaxDynamicSharedMemorySize, GSMEM);
    cudaFuncSetAttribute(gemm_mma<2>, cudaFuncAttributeMaxDynamicSharedMemorySize, GSMEM);
    cudaFuncSetAttribute(attn_mma, cudaFuncAttributeMaxDynamicSharedMemorySize, ASMEM);

    dim3 sgrid((MROWS * DDIM) / 4 / 256, 1, 2);        // (8192,1,2)
    dim3 tgrid(32, 32, 4), tblk(256);
    dim3 ggrid(DDIM / 256, MROWS / 256);                // (4, 32) = 128 CTAs

    // prep: splits + weight transposes (merged launches)
    split2_kernel<<<sgrid, 256>>>(x, y, axh, axl, ayh, ayl);
    tsplit4_kernel<<<tgrid, tblk>>>(Wq, Wk, Wv, Wf, wth, wtl);

    // projections -> bf16 hi/lo directly
    gemm_mma<2><<<ggrid, 512, GSMEM>>>(axh, axl, wth + 0 * WSZ, wtl + 0 * WSZ, bq, nullptr, nullptr, qh, ql);
    gemm_mma<2><<<ggrid, 512, GSMEM>>>(ayh, ayl, wth + 1 * WSZ, wtl + 1 * WSZ, bk, nullptr, nullptr, kh, kl);
    gemm_mma<2><<<ggrid, 512, GSMEM>>>(ayh, ayl, wth + 2 * WSZ, wtl + 2 * WSZ, bv, nullptr, nullptr, vh, vl);

    // attention (tensor cores, q-tile 256, 16 warps)
    attn_mma<<<dim3(NSEQ / 256, BB * NH), 512, ASMEM>>>(qh, ql, kh, kl, vh, vl, pao);

    // LN1(x + attn) -> fp32 h1 AND bf16 hi/lo split
    ln_kernel<<<MROWS, 256>>>(x, pao, g1, b1, ph1, axh, axl);

    // FF: t = relu(h1 @ Wf + bf) + h1
    gemm_mma<1><<<ggrid, 512, GSMEM>>>(axh, axl, wth + 3 * WSZ, wtl + 3 * WSZ, bf, ph1, pt, nullptr, nullptr);

    // LN2
    ln_kernel<<<MROWS, 256>>>(pt, nullptr, g2, b2, out, nullptr, nullptr);
}

// round 10
// speedup vs baseline: 11.5048x; 11.5048x over previous
#include <cuda_runtime.h>
#include <cuda_bf16.h>
#include <math.h>
#include <stdint.h>

// Problem constants
#define BB    8
#define NSEQ  1024
#define DDIM  1024
#define NH    16
#define DHEAD 64
#define MROWS (BB * NSEQ)   // 8192

// ============================ PTX helpers ====================================
__device__ __forceinline__ uint32_t smem_u32(const void* p) {
    uint32_t a;
    asm("{ .reg .u64 t; cvta.to.shared.u64 t, %1; cvt.u32.u64 %0, t; }" : "=r"(a) : "l"(p));
    return a;
}
__device__ __forceinline__ void cp16(uint32_t d, const void* s) {
    asm volatile("cp.async.cg.shared.global [%0], [%1], 16;" :: "r"(d), "l"(s) : "memory");
}
#define CP_COMMIT() asm volatile("cp.async.commit_group;" ::: "memory")
#define CP_WAIT(n)  asm volatile("cp.async.wait_group %0;" :: "n"(n) : "memory")

__device__ __forceinline__ void ldsm4(uint32_t* r, uint32_t a) {
    asm volatile("ldmatrix.sync.aligned.m8n8.x4.shared.b16 {%0,%1,%2,%3}, [%4];"
        : "=r"(r[0]), "=r"(r[1]), "=r"(r[2]), "=r"(r[3]) : "r"(a));
}
__device__ __forceinline__ void ldsm4t(uint32_t* r, uint32_t a) {
    asm volatile("ldmatrix.sync.aligned.m8n8.x4.trans.shared.b16 {%0,%1,%2,%3}, [%4];"
        : "=r"(r[0]), "=r"(r[1]), "=r"(r[2]), "=r"(r[3]) : "r"(a));
}
__device__ __forceinline__ void mma16816(float* c, const uint32_t* a, const uint32_t* b) {
    asm volatile("mma.sync.aligned.m16n8k16.row.col.f32.bf16.bf16.f32 "
        "{%0,%1,%2,%3}, {%4,%5,%6,%7}, {%8,%9}, {%0,%1,%2,%3};"
        : "+f"(c[0]), "+f"(c[1]), "+f"(c[2]), "+f"(c[3])
        : "r"(a[0]), "r"(a[1]), "r"(a[2]), "r"(a[3]), "r"(b[0]), "r"(b[1]));
}
__device__ __forceinline__ void hi_lo_pack(float x, float y, uint32_t& h, uint32_t& l) {
    __nv_bfloat16 hx = __float2bfloat16(x), hy = __float2bfloat16(y);
    __nv_bfloat16 lx = __float2bfloat16(x - __bfloat162float(hx));
    __nv_bfloat16 ly = __float2bfloat16(y - __bfloat162float(hy));
    __nv_bfloat162 hv(hx, hy), lv(lx, ly);
    h = *(uint32_t*)&hv; l = *(uint32_t*)&lv;
}

// ============================ scratch buffers ================================
__device__ float g_ao[(size_t)MROWS * DDIM];
__device__ float g_h1[(size_t)MROWS * DDIM];
__device__ float g_t [(size_t)MROWS * DDIM];

__device__ __align__(1024) __nv_bfloat16 g_axh[(size_t)MROWS * DDIM];
__device__ __align__(1024) __nv_bfloat16 g_axl[(size_t)MROWS * DDIM];
__device__ __align__(1024) __nv_bfloat16 g_ayh[(size_t)MROWS * DDIM];
__device__ __align__(1024) __nv_bfloat16 g_ayl[(size_t)MROWS * DDIM];
__device__ __align__(1024) __nv_bfloat16 g_wth[4][(size_t)DDIM * DDIM];
__device__ __align__(1024) __nv_bfloat16 g_wtl[4][(size_t)DDIM * DDIM];
__device__ __align__(1024) __nv_bfloat16 g_qh[(size_t)MROWS * DDIM];
__device__ __align__(1024) __nv_bfloat16 g_ql[(size_t)MROWS * DDIM];
__device__ __align__(1024) __nv_bfloat16 g_kh[(size_t)MROWS * DDIM];
__device__ __align__(1024) __nv_bfloat16 g_kl[(size_t)MROWS * DDIM];
__device__ __align__(1024) __nv_bfloat16 g_vh[(size_t)MROWS * DDIM];
__device__ __align__(1024) __nv_bfloat16 g_vl[(size_t)MROWS * DDIM];

// ============================ split / transpose (merged launches) ============
// z=0: split x ; z=1: split y
__global__ __launch_bounds__(256)
void split2_kernel(const float* __restrict__ in0, const float* __restrict__ in1,
                   __nv_bfloat16* __restrict__ hi0, __nv_bfloat16* __restrict__ lo0,
                   __nv_bfloat16* __restrict__ hi1, __nv_bfloat16* __restrict__ lo1)
{
    const float* in = blockIdx.z ? in1 : in0;
    __nv_bfloat16* hi = blockIdx.z ? hi1 : hi0;
    __nv_bfloat16* lo = blockIdx.z ? lo1 : lo0;
    int i = blockIdx.x * 256 + threadIdx.x;
    float4 v = ((const float4*)in)[i];
    uint32_t h01, l01, h23, l23;
    hi_lo_pack(v.x, v.y, h01, l01);
    hi_lo_pack(v.z, v.w, h23, l23);
    uint2 hw, lw;
    hw.x = h01; hw.y = h23; lw.x = l01; lw.y = l23;
    ((uint2*)hi)[i] = hw;
    ((uint2*)lo)[i] = lw;
}

// 4 weights transposed+split in one launch (z selects weight)
__global__ __launch_bounds__(256)
void tsplit4_kernel(const float* __restrict__ W0, const float* __restrict__ W1,
                    const float* __restrict__ W2, const float* __restrict__ W3,
                    __nv_bfloat16* __restrict__ thb, __nv_bfloat16* __restrict__ tlb)
{
    const int w = blockIdx.z;
    const float* W = (w == 0) ? W0 : (w == 1) ? W1 : (w == 2) ? W2 : W3;
    __nv_bfloat16* th = thb + (size_t)w * DDIM * DDIM;
    __nv_bfloat16* tl = tlb + (size_t)w * DDIM * DDIM;

    __shared__ float t[32][33];
    const int tx = threadIdx.x & 31;
    const int ty = threadIdx.x >> 5;
    const int kb = blockIdx.y * 32;
    const int nb = blockIdx.x * 32;
#pragma unroll
    for (int i = 0; i < 4; i++) {
        int kk = ty + i * 8;
        t[kk][tx] = W[(size_t)(kb + kk) * DDIM + nb + tx];
    }
    __syncthreads();
#pragma unroll
    for (int i = 0; i < 4; i++) {
        int nn = ty + i * 8;
        float v = t[tx][nn];
        __nv_bfloat16 h = __float2bfloat16(v);
        __nv_bfloat16 l = __float2bfloat16(v - __bfloat162float(h));
        size_t o = (size_t)(nb + nn) * DDIM + kb + tx;
        th[o] = h; tl[o] = l;
    }
}

// ============================ HMMA GEMM (bf16 split, fp32 acc) ===============
// PROVEN R8 config: BM=256, BN=128, BK=64, 256 threads, warp tile 64x64
// (4m x 2n warps), 2 stages. 256 threads -> 256-reg/thread budget (no spill).
// EPI 0: C = A@W + b. EPI 1: C = relu(A@W+b)+res. EPI 2: bf16 hi/lo split out.
#define G_SST   144                      // smem row stride bytes (72 bf16)
#define G_ATILE (256 * G_SST)            // 36864
#define G_BTILE (128 * G_SST)            // 18432
#define G_STAGE (2 * G_ATILE + 2 * G_BTILE)   // 110592
#define GSMEM   (2 * G_STAGE)            // 221184

template <int EPI>
__global__ __launch_bounds__(256)
void gemm_mma(const __nv_bfloat16* __restrict__ Ah_, const __nv_bfloat16* __restrict__ Al_,
              const __nv_bfloat16* __restrict__ Bh_, const __nv_bfloat16* __restrict__ Bl_,
              const float* __restrict__ bias, const float* __restrict__ res,
              float* __restrict__ C,
              __nv_bfloat16* __restrict__ Ch, __nv_bfloat16* __restrict__ Cl)
{
    extern __shared__ __align__(128) char gsm[];
    const uint32_t sb = smem_u32(gsm);
    const int tid = threadIdx.x, lid = tid & 31, wid = tid >> 5;
    const int wm = (wid & 3) * 64, wn = (wid >> 2) * 64;
    const int bm = blockIdx.y * 256, bn = blockIdx.x * 128;

    const uint32_t aoff = (uint32_t)(wm + (lid & 15)) * G_SST + (((lid >> 4) & 1) * 16);
    const uint32_t boff = (uint32_t)(((lid >> 4) & 1) * 8 + (lid & 7)) * G_SST
                        + (((lid >> 3) & 1) * 16);

    float acc[4][8][4];
#pragma unroll
    for (int i = 0; i < 4; i++)
#pragma unroll
        for (int j = 0; j < 8; j++)
#pragma unroll
            for (int e = 0; e < 4; e++) acc[i][j][e] = 0.0f;

    auto LOAD = [&](int stg, int k0) {
        const uint32_t s = sb + (uint32_t)stg * G_STAGE;
#pragma unroll
        for (int t = 0; t < 8; t++) {           // A: 2048 cp16 per tensor
            int idx = tid + t * 256;
            int r = idx >> 3, sg = idx & 7;
            uint32_t so = (uint32_t)r * G_SST + sg * 16;
            size_t go = (size_t)(bm + r) * DDIM + k0 + sg * 8;
            cp16(s + so,           Ah_ + go);
            cp16(s + G_ATILE + so, Al_ + go);
        }
#pragma unroll
        for (int t = 0; t < 4; t++) {           // B: 1024 cp16 per tensor
            int idx = tid + t * 256;
            int r = idx >> 3, sg = idx & 7;
            uint32_t so = (uint32_t)r * G_SST + sg * 16;
            size_t go = (size_t)(bn + r) * DDIM + k0 + sg * 8;
            cp16(s + 2 * G_ATILE + so,           Bh_ + go);
            cp16(s + 2 * G_ATILE + G_BTILE + so, Bl_ + go);
        }
    };

    LOAD(0, 0);
    CP_COMMIT();

    for (int c = 0; c < 16; c++) {
        if (c + 1 < 16) { LOAD((c + 1) & 1, (c + 1) * 64); CP_COMMIT(); CP_WAIT(1); }
        else            { CP_WAIT(0); }
        __syncthreads();
        const uint32_t st = sb + (uint32_t)(c & 1) * G_STAGE;

#pragma unroll
        for (int s = 0; s < 4; s++) {
            const uint32_t ks = s * 32;          // 16 bf16 per k-step
            uint32_t AH[4][4], AL[4][4];
#pragma unroll
            for (int i = 0; i < 4; i++) {
                ldsm4(AH[i], st + aoff + (uint32_t)(i * 16) * G_SST + ks);
                ldsm4(AL[i], st + G_ATILE + aoff + (uint32_t)(i * 16) * G_SST + ks);
            }
#pragma unroll
            for (int g = 0; g < 4; g++) {
                uint32_t BH[4], BL[4];
                const uint32_t ba = st + 2 * G_ATILE
                                  + (uint32_t)(wn + g * 16) * G_SST + boff + ks;
                ldsm4(BH, ba);
                ldsm4(BL, ba + G_BTILE);
#pragma unroll
                for (int i = 0; i < 4; i++) {
                    mma16816(acc[i][2 * g],     AH[i], &BH[0]);
                    mma16816(acc[i][2 * g + 1], AH[i], &BH[2]);
                }
#pragma unroll
                for (int i = 0; i < 4; i++) {
                    mma16816(acc[i][2 * g],     AL[i], &BH[0]);
                    mma16816(acc[i][2 * g + 1], AL[i], &BH[2]);
                }
#pragma unroll
                for (int i = 0; i < 4; i++) {
                    mma16816(acc[i][2 * g],     AH[i], &BL[0]);
                    mma16816(acc[i][2 * g + 1], AH[i], &BL[2]);
                }
            }
        }
        __syncthreads();
    }

    // epilogue
    const int gr = lid >> 2, gc = (lid & 3) * 2;
#pragma unroll
    for (int i = 0; i < 4; i++) {
        const int r0 = bm + wm + i * 16 + gr;
        const int r1 = r0 + 8;
#pragma unroll
        for (int j = 0; j < 8; j++) {
            const int col = bn + wn + j * 8 + gc;
            const float bx = bias[col], by = bias[col + 1];
            float v0 = acc[i][j][0] + bx, v1 = acc[i][j][1] + by;
            float v2 = acc[i][j][2] + bx, v3 = acc[i][j][3] + by;
            if (EPI == 2) {
                uint32_t h01, l01, h23, l23;
                hi_lo_pack(v0, v1, h01, l01);
                hi_lo_pack(v2, v3, h23, l23);
                *(uint32_t*)(Ch + (size_t)r0 * DDIM + col) = h01;
                *(uint32_t*)(Cl + (size_t)r0 * DDIM + col) = l01;
                *(uint32_t*)(Ch + (size_t)r1 * DDIM + col) = h23;
                *(uint32_t*)(Cl + (size_t)r1 * DDIM + col) = l23;
            } else {
                if (EPI == 1) {
                    const float* rp0 = res + (size_t)r0 * DDIM + col;
                    const float* rp1 = res + (size_t)r1 * DDIM + col;
                    v0 = fmaxf(v0, 0.0f) + rp0[0];
                    v1 = fmaxf(v1, 0.0f) + rp0[1];
                    v2 = fmaxf(v2, 0.0f) + rp1[0];
                    v3 = fmaxf(v3, 0.0f) + rp1[1];
                }
                *(float2*)(C + (size_t)r0 * DDIM + col) = make_float2(v0, v1);
                *(float2*)(C + (size_t)r1 * DDIM + col) = make_float2(v2, v3);
            }
        }
    }
}

// ============================ HMMA flash attention ===========================
// PROVEN R8 config: CTA = 128 q-rows of one (b,h), 256 threads (8 warps x 16
// rows). K/V chunks of 128, 2-stage.
#define AST_B   144
#define ATILE_B (128 * AST_B)
#define ASMEM   (10 * ATILE_B)

__global__ __launch_bounds__(256, 1)
void attn_mma(const __nv_bfloat16* __restrict__ Qh_g, const __nv_bfloat16* __restrict__ Ql_g,
              const __nv_bfloat16* __restrict__ Kh_g, const __nv_bfloat16* __restrict__ Kl_g,
              const __nv_bfloat16* __restrict__ Vh_g, const __nv_bfloat16* __restrict__ Vl_g,
              float* __restrict__ O)
{
    extern __shared__ __align__(128) char asm_[];
    const uint32_t sb = smem_u32(asm_);
    const int tid = threadIdx.x, lid = tid & 31, wid = tid >> 5;
    const int bh = blockIdx.y, b = bh >> 4, h = bh & 15;
    const int q0 = blockIdx.x * 128;

    const size_t qbase = (size_t)(b * NSEQ + q0) * DDIM + h * DHEAD;
    const size_t kbase = (size_t)(b * NSEQ) * DDIM + h * DHEAD;

    const uint32_t sQh = sb, sQl = sb + ATILE_B;
    const uint32_t aoff = (uint32_t)(16 * wid + (lid & 15)) * AST_B + ((lid >> 4) & 1) * 16;
    const uint32_t boff = (uint32_t)(((lid >> 4) & 1) * 8 + (lid & 7)) * AST_B
                        + ((lid >> 3) & 1) * 16;
    const uint32_t voff = (uint32_t)(lid & 15) * AST_B + ((lid >> 4) & 1) * 16;

    auto loadKV = [&](int kt, int st) {
        const uint32_t base = sb + 2 * ATILE_B + (uint32_t)st * (4 * ATILE_B);
        const size_t gk = kbase + (size_t)(kt * 128) * DDIM;
        for (int i = tid; i < 1024; i += 256) {
            int r = i >> 3, sg = i & 7;
            uint32_t so = (uint32_t)r * AST_B + sg * 16;
            size_t go = gk + (size_t)r * DDIM + sg * 8;
            cp16(base + so,               Kh_g + go);
            cp16(base + ATILE_B + so,     Kl_g + go);
            cp16(base + 2 * ATILE_B + so, Vh_g + go);
            cp16(base + 3 * ATILE_B + so, Vl_g + go);
        }
    };

    for (int i = tid; i < 1024; i += 256) {
        int r = i >> 3, sg = i & 7;
        uint32_t so = (uint32_t)r * AST_B + sg * 16;
        size_t go = qbase + (size_t)r * DDIM + sg * 8;
        cp16(sQh + so, Qh_g + go);
        cp16(sQl + so, Ql_g + go);
    }
    loadKV(0, 0);
    CP_COMMIT();
    loadKV(1, 1);
    CP_COMMIT();
    CP_WAIT(1);
    __syncthreads();

    float m0 = -1e30f, m1 = -1e30f, l0v = 0.0f, l1v = 0.0f;
    float ov[8][4];
#pragma unroll
    for (int j = 0; j < 8; j++)
#pragma unroll
        for (int e = 0; e < 4; e++) ov[j][e] = 0.0f;

    for (int kt = 0; kt < 8; kt++) {
        const uint32_t kvb = sb + 2 * ATILE_B + (uint32_t)(kt & 1) * (4 * ATILE_B);

        float sacc[16][4];
#pragma unroll
        for (int t = 0; t < 16; t++)
#pragma unroll
            for (int e = 0; e < 4; e++) sacc[t][e] = 0.0f;

#pragma unroll
        for (int kk = 0; kk < 4; kk++) {
            uint32_t QH[4], QL[4];
            ldsm4(QH, sQh + aoff + kk * 32);
            ldsm4(QL, sQl + aoff + kk * 32);
#pragma unroll
            for (int n = 0; n < 8; n++) {
                uint32_t KB[4];
                ldsm4(KB, kvb + boff + (uint32_t)n * (16 * AST_B) + kk * 32);
                mma16816(sacc[2 * n],     QH, &KB[0]);
                mma16816(sacc[2 * n + 1], QH, &KB[2]);
                mma16816(sacc[2 * n],     QL, &KB[0]);
                mma16816(sacc[2 * n + 1], QL, &KB[2]);
                ldsm4(KB, kvb + ATILE_B + boff + (uint32_t)n * (16 * AST_B) + kk * 32);
                mma16816(sacc[2 * n],     QH, &KB[0]);
                mma16816(sacc[2 * n + 1], QH, &KB[2]);
            }
        }

        const float scale = 0.03125f;
        float mx0 = -1e30f, mx1 = -1e30f;
#pragma unroll
        for (int t = 0; t < 16; t++) {
            sacc[t][0] *= scale; sacc[t][1] *= scale;
            sacc[t][2] *= scale; sacc[t][3] *= scale;
            mx0 = fmaxf(mx0, fmaxf(sacc[t][0], sacc[t][1]));
            mx1 = fmaxf(mx1, fmaxf(sacc[t][2], sacc[t][3]));
        }
        mx0 = fmaxf(mx0, __shfl_xor_sync(0xffffffffu, mx0, 1));
        mx0 = fmaxf(mx0, __shfl_xor_sync(0xffffffffu, mx0, 2));
        mx1 = fmaxf(mx1, __shfl_xor_sync(0xffffffffu, mx1, 1));
        mx1 = fmaxf(mx1, __shfl_xor_sync(0xffffffffu, mx1, 2));
        const float mn0 = fmaxf(m0, mx0), mn1 = fmaxf(m1, mx1);
        const float a0 = __expf(m0 - mn0), a1 = __expf(m1 - mn1);
        float rs0 = 0.0f, rs1 = 0.0f;
#pragma unroll
        for (int t = 0; t < 16; t++) {
            float e0 = __expf(sacc[t][0] - mn0);
            float e1 = __expf(sacc[t][1] - mn0);
            float e2 = __expf(sacc[t][2] - mn1);
            float e3 = __expf(sacc[t][3] - mn1);
            sacc[t][0] = e0; sacc[t][1] = e1; sacc[t][2] = e2; sacc[t][3] = e3;
            rs0 += e0 + e1; rs1 += e2 + e3;
        }
        rs0 += __shfl_xor_sync(0xffffffffu, rs0, 1);
        rs0 += __shfl_xor_sync(0xffffffffu, rs0, 2);
        rs1 += __shfl_xor_sync(0xffffffffu, rs1, 1);
        rs1 += __shfl_xor_sync(0xffffffffu, rs1, 2);
        l0v = l0v * a0 + rs0;
        l1v = l1v * a1 + rs1;
        m0 = mn0; m1 = mn1;
#pragma unroll
        for (int j = 0; j < 8; j++) {
            ov[j][0] *= a0; ov[j][1] *= a0;
            ov[j][2] *= a1; ov[j][3] *= a1;
        }

        const uint32_t sVh = kvb + 2 * ATILE_B, sVl = kvb + 3 * ATILE_B;
#pragma unroll
        for (int t = 0; t < 8; t++) {
            uint32_t aPh[4], aPl[4];
            hi_lo_pack(sacc[2 * t][0],     sacc[2 * t][1],     aPh[0], aPl[0]);
            hi_lo_pack(sacc[2 * t][2],     sacc[2 * t][3],     aPh[1], aPl[1]);
            hi_lo_pack(sacc[2 * t + 1][0], sacc[2 * t + 1][1], aPh[2], aPl[2]);
            hi_lo_pack(sacc[2 * t + 1][2], sacc[2 * t + 1][3], aPh[3], aPl[3]);
#pragma unroll
            for (int nv = 0; nv < 4; nv++) {
                uint32_t VB[4];
                ldsm4t(VB, sVh + voff + (uint32_t)t * (16 * AST_B) + nv * 32);
                mma16816(ov[2 * nv],     aPh, &VB[0]);
                mma16816(ov[2 * nv + 1], aPh, &VB[2]);
                mma16816(ov[2 * nv],     aPl, &VB[0]);
                mma16816(ov[2 * nv + 1], aPl, &VB[2]);
                ldsm4t(VB, sVl + voff + (uint32_t)t * (16 * AST_B) + nv * 32);
                mma16816(ov[2 * nv],     aPh, &VB[0]);
                mma16816(ov[2 * nv + 1], aPh, &VB[2]);
            }
        }

        __syncthreads();
        if (kt + 2 < 8) {
            loadKV(kt + 2, kt & 1);
            CP_COMMIT();
            CP_WAIT(1);
            __syncthreads();
        } else if (kt + 1 < 8) {
            CP_WAIT(0);
            __syncthreads();
        }
    }

    const float inv0 = 1.0f / l0v, inv1 = 1.0f / l1v;
    const int gr = lid >> 2, gc = (lid & 3) * 2;
    float* op0 = O + (size_t)(b * NSEQ + q0 + 16 * wid + gr) * DDIM + h * DHEAD;
    float* op1 = op0 + 8 * DDIM;
#pragma unroll
    for (int j = 0; j < 8; j++) {
        *(float2*)(op0 + j * 8 + gc) = make_float2(ov[j][0] * inv0, ov[j][1] * inv0);
        *(float2*)(op1 + j * 8 + gc) = make_float2(ov[j][2] * inv1, ov[j][3] * inv1);
    }
}

// ============================ LayerNorm (+ optional bf16 split out) ==========
__global__ __launch_bounds__(256)
void ln_kernel(const float* __restrict__ A, const float* __restrict__ R,
               const float* __restrict__ gamma, const float* __restrict__ beta,
               float* __restrict__ out,
               __nv_bfloat16* __restrict__ hi, __nv_bfloat16* __restrict__ lo)
{
    const int row = blockIdx.x;
    const int tid = threadIdx.x;
    const size_t base = (size_t)row * DDIM + tid * 4;

    float4 v = *(const float4*)(A + base);
    if (R != nullptr) {
        float4 r = *(const float4*)(R + base);
        v.x += r.x; v.y += r.y; v.z += r.z; v.w += r.w;
    }

    __shared__ float red1[8];
    __shared__ float red2[8];

    float s = v.x + v.y + v.z + v.w;
#pragma unroll
    for (int off = 16; off > 0; off >>= 1) s += __shfl_xor_sync(0xffffffffu, s, off);
    if ((tid & 31) == 0) red1[tid >> 5] = s;
    __syncthreads();
    float tot = 0.0f;
#pragma unroll
    for (int k = 0; k < 8; k++) tot += red1[k];
    float mean = tot * (1.0f / 1024.0f);

    float d0 = v.x - mean, d1 = v.y - mean, d2 = v.z - mean, d3 = v.w - mean;
    float sq = d0 * d0 + d1 * d1 + d2 * d2 + d3 * d3;
#pragma unroll
    for (int off = 16; off > 0; off >>= 1) sq += __shfl_xor_sync(0xffffffffu, sq, off);
    if ((tid & 31) == 0) red2[tid >> 5] = sq;
    __syncthreads();
    float vtot = 0.0f;
#pragma unroll
    for (int k = 0; k < 8; k++) vtot += red2[k];
    float rstd = rsqrtf(vtot * (1.0f / 1024.0f) + 1e-6f);

    float4 g4 = *(const float4*)(gamma + tid * 4);
    float4 b4 = *(const float4*)(beta  + tid * 4);
    float4 o4 = make_float4(d0 * rstd * g4.x + b4.x,
                            d1 * rstd * g4.y + b4.y,
                            d2 * rstd * g4.z + b4.z,
                            d3 * rstd * g4.w + b4.w);
    *(float4*)(out + base) = o4;

    if (hi != nullptr) {
        uint32_t h01, l01, h23, l23;
        hi_lo_pack(o4.x, o4.y, h01, l01);
        hi_lo_pack(o4.z, o4.w, h23, l23);
        uint2 hw, lw;
        hw.x = h01; hw.y = h23;
        lw.x = l01; lw.y = l23;
        *(uint2*)(hi + base) = hw;
        *(uint2*)(lo + base) = lw;
    }
}

// ============================ host launch ====================================
extern "C" void kernel_launch(void* const* d_in, const int* in_sizes, int n_in,
                              void* d_out, int out_size)
{
    (void)in_sizes; (void)n_in; (void)out_size;
    const float* x  = (const float*)d_in[0];
    const float* y  = (const float*)d_in[1];
    const float* Wq = (const float*)d_in[2];
    const float* bq = (const float*)d_in[3];
    const float* Wk = (const float*)d_in[4];
    const float* bk = (const float*)d_in[5];
    const float* Wv = (const float*)d_in[6];
    const float* bv = (const float*)d_in[7];
    const float* Wf = (const float*)d_in[8];
    const float* bf = (const float*)d_in[9];
    const float* g1 = (const float*)d_in[10];
    const float* b1 = (const float*)d_in[11];
    const float* g2 = (const float*)d_in[12];
    const float* b2 = (const float*)d_in[13];
    float* out = (float*)d_out;

    float *pao, *ph1, *pt;
    cudaGetSymbolAddress((void**)&pao, g_ao);
    cudaGetSymbolAddress((void**)&ph1, g_h1);
    cudaGetSymbolAddress((void**)&pt,  g_t);

    void *paxh, *paxl, *payh, *payl, *pwth, *pwtl;
    void *pqh, *pql, *pkh, *pkl, *pvh, *pvl;
    cudaGetSymbolAddress(&paxh, g_axh);
    cudaGetSymbolAddress(&paxl, g_axl);
    cudaGetSymbolAddress(&payh, g_ayh);
    cudaGetSymbolAddress(&payl, g_ayl);
    cudaGetSymbolAddress(&pwth, g_wth);
    cudaGetSymbolAddress(&pwtl, g_wtl);
    cudaGetSymbolAddress(&pqh, g_qh);
    cudaGetSymbolAddress(&pql, g_ql);
    cudaGetSymbolAddress(&pkh, g_kh);
    cudaGetSymbolAddress(&pkl, g_kl);
    cudaGetSymbolAddress(&pvh, g_vh);
    cudaGetSymbolAddress(&pvl, g_vl);

    __nv_bfloat16* axh = (__nv_bfloat16*)paxh;
    __nv_bfloat16* axl = (__nv_bfloat16*)paxl;
    __nv_bfloat16* ayh = (__nv_bfloat16*)payh;
    __nv_bfloat16* ayl = (__nv_bfloat16*)payl;
    __nv_bfloat16* wth = (__nv_bfloat16*)pwth;
    __nv_bfloat16* wtl = (__nv_bfloat16*)pwtl;
    __nv_bfloat16* qh = (__nv_bfloat16*)pqh;
    __nv_bfloat16* ql = (__nv_bfloat16*)pql;
    __nv_bfloat16* kh = (__nv_bfloat16*)pkh;
    __nv_bfloat16* kl = (__nv_bfloat16*)pkl;
    __nv_bfloat16* vh = (__nv_bfloat16*)pvh;
    __nv_bfloat16* vl = (__nv_bfloat16*)pvl;
    const size_t WSZ = (size_t)DDIM * DDIM;

    cudaFuncSetAttribute(gemm_mma<0>, cudaFuncAttributeMaxDynamicSharedMemorySize, GSMEM);
    cudaFuncSetAttribute(gemm_mma<1>, cudaFuncAttributeMaxDynamicSharedMemorySize, GSMEM);
    cudaFuncSetAttribute(gemm_mma<2>, cudaFuncAttributeMaxDynamicSharedMemorySize, GSMEM);
    cudaFuncSetAttribute(attn_mma, cudaFuncAttributeMaxDynamicSharedMemorySize, ASMEM);

    dim3 sgrid((MROWS * DDIM) / 4 / 256, 1, 2);        // (8192,1,2)
    dim3 tgrid(32, 32, 4), tblk(256);
    dim3 ggrid(DDIM / 128, MROWS / 256);                // (8, 32) = 256 CTAs

    // prep: splits + weight transposes (merged launches)
    split2_kernel<<<sgrid, 256>>>(x, y, axh, axl, ayh, ayl);
    tsplit4_kernel<<<tgrid, tblk>>>(Wq, Wk, Wv, Wf, wth, wtl);

    // projections -> bf16 hi/lo directly
    gemm_mma<2><<<ggrid, 256, GSMEM>>>(axh, axl, wth + 0 * WSZ, wtl + 0 * WSZ, bq, nullptr, nullptr, qh, ql);
    gemm_mma<2><<<ggrid, 256, GSMEM>>>(ayh, ayl, wth + 1 * WSZ, wtl + 1 * WSZ, bk, nullptr, nullptr, kh, kl);
    gemm_mma<2><<<ggrid, 256, GSMEM>>>(ayh, ayl, wth + 2 * WSZ, wtl + 2 * WSZ, bv, nullptr, nullptr, vh, vl);

    // attention (tensor cores)
    attn_mma<<<dim3(NSEQ / 128, BB * NH), 256, ASMEM>>>(qh, ql, kh, kl, vh, vl, pao);

    // LN1(x + attn) -> fp32 h1 AND bf16 hi/lo split
    ln_kernel<<<MROWS, 256>>>(x, pao, g1, b1, ph1, axh, axl);

    // FF: t = relu(h1 @ Wf + bf) + h1
    gemm_mma<1><<<ggrid, 256, GSMEM>>>(axh, axl, wth + 3 * WSZ, wtl + 3 * WSZ, bf, ph1, pt, nullptr, nullptr);

    // LN2
    ln_kernel<<<MROWS, 256>>>(pt, nullptr, g2, b2, out, nullptr, nullptr);
}

// round 11
// speedup vs baseline: 15.3905x; 1.3378x over previous
#include <cuda_runtime.h>
#include <cuda_fp16.h>
#include <math.h>
#include <stdint.h>

// Problem constants
#define BB    8
#define NSEQ  1024
#define DDIM  1024
#define NH    16
#define DHEAD 64
#define MROWS (BB * NSEQ)   // 8192

// ============================ PTX helpers ====================================
__device__ __forceinline__ uint32_t smem_u32(const void* p) {
    uint32_t a;
    asm("{ .reg .u64 t; cvta.to.shared.u64 t, %1; cvt.u32.u64 %0, t; }" : "=r"(a) : "l"(p));
    return a;
}
__device__ __forceinline__ void cp16(uint32_t d, const void* s) {
    asm volatile("cp.async.cg.shared.global [%0], [%1], 16;" :: "r"(d), "l"(s) : "memory");
}
#define CP_COMMIT() asm volatile("cp.async.commit_group;" ::: "memory")
#define CP_WAIT(n)  asm volatile("cp.async.wait_group %0;" :: "n"(n) : "memory")

__device__ __forceinline__ void ldsm4(uint32_t* r, uint32_t a) {
    asm volatile("ldmatrix.sync.aligned.m8n8.x4.shared.b16 {%0,%1,%2,%3}, [%4];"
        : "=r"(r[0]), "=r"(r[1]), "=r"(r[2]), "=r"(r[3]) : "r"(a));
}
__device__ __forceinline__ void ldsm4t(uint32_t* r, uint32_t a) {
    asm volatile("ldmatrix.sync.aligned.m8n8.x4.trans.shared.b16 {%0,%1,%2,%3}, [%4];"
        : "=r"(r[0]), "=r"(r[1]), "=r"(r[2]), "=r"(r[3]) : "r"(a));
}
// fp16 in, fp32 accumulate
__device__ __forceinline__ void mma16816(float* c, const uint32_t* a, const uint32_t* b) {
    asm volatile("mma.sync.aligned.m16n8k16.row.col.f32.f16.f16.f32 "
        "{%0,%1,%2,%3}, {%4,%5,%6,%7}, {%8,%9}, {%0,%1,%2,%3};"
        : "+f"(c[0]), "+f"(c[1]), "+f"(c[2]), "+f"(c[3])
        : "r"(a[0]), "r"(a[1]), "r"(a[2]), "r"(a[3]), "r"(b[0]), "r"(b[1]));
}
__device__ __forceinline__ void hi_lo_pack(float x, float y, uint32_t& h, uint32_t& l) {
    __half hx = __float2half_rn(x), hy = __float2half_rn(y);
    __half lx = __float2half_rn(x - __half2float(hx));
    __half ly = __float2half_rn(y - __half2float(hy));
    __half2 hv = __halves2half2(hx, hy), lv = __halves2half2(lx, ly);
    h = *(uint32_t*)&hv; l = *(uint32_t*)&lv;
}
__device__ __forceinline__ uint32_t hi_pack(float x, float y) {
    __half2 hv = __halves2half2(__float2half_rn(x), __float2half_rn(y));
    return *(uint32_t*)&hv;
}

// ============================ scratch buffers ================================
__device__ float g_ao[(size_t)MROWS * DDIM];
__device__ float g_h1[(size_t)MROWS * DDIM];
__device__ float g_t [(size_t)MROWS * DDIM];

__device__ __align__(1024) __half g_axh[(size_t)MROWS * DDIM];
__device__ __align__(1024) __half g_axl[(size_t)MROWS * DDIM];
__device__ __align__(1024) __half g_ayh[(size_t)MROWS * DDIM];
__device__ __align__(1024) __half g_ayl[(size_t)MROWS * DDIM];
__device__ __align__(1024) __half g_wth[4][(size_t)DDIM * DDIM];   // weights hi only
__device__ __align__(1024) __half g_qh[(size_t)MROWS * DDIM];
__device__ __align__(1024) __half g_ql[(size_t)MROWS * DDIM];
__device__ __align__(1024) __half g_kh[(size_t)MROWS * DDIM];      // K hi only
__device__ __align__(1024) __half g_vh[(size_t)MROWS * DDIM];      // V hi only

// ============================ split / transpose (merged launches) ============
// z=0: split x ; z=1: split y
__global__ __launch_bounds__(256)
void split2_kernel(const float* __restrict__ in0, const float* __restrict__ in1,
                   __half* __restrict__ hi0, __half* __restrict__ lo0,
                   __half* __restrict__ hi1, __half* __restrict__ lo1)
{
    const float* in = blockIdx.z ? in1 : in0;
    __half* hi = blockIdx.z ? hi1 : hi0;
    __half* lo = blockIdx.z ? lo1 : lo0;
    int i = blockIdx.x * 256 + threadIdx.x;
    float4 v = ((const float4*)in)[i];
    uint32_t h01, l01, h23, l23;
    hi_lo_pack(v.x, v.y, h01, l01);
    hi_lo_pack(v.z, v.w, h23, l23);
    uint2 hw, lw;
    hw.x = h01; hw.y = h23; lw.x = l01; lw.y = l23;
    ((uint2*)hi)[i] = hw;
    ((uint2*)lo)[i] = lw;
}

// 4 weights transposed in one launch (z selects weight); hi-only fp16
__global__ __launch_bounds__(256)
void tsplit4_kernel(const float* __restrict__ W0, const float* __restrict__ W1,
                    const float* __restrict__ W2, const float* __restrict__ W3,
                    __half* __restrict__ thb)
{
    const int w = blockIdx.z;
    const float* W = (w == 0) ? W0 : (w == 1) ? W1 : (w == 2) ? W2 : W3;
    __half* th = thb + (size_t)w * DDIM * DDIM;

    __shared__ float t[32][33];
    const int tx = threadIdx.x & 31;
    const int ty = threadIdx.x >> 5;
    const int kb = blockIdx.y * 32;
    const int nb = blockIdx.x * 32;
#pragma unroll
    for (int i = 0; i < 4; i++) {
        int kk = ty + i * 8;
        t[kk][tx] = W[(size_t)(kb + kk) * DDIM + nb + tx];
    }
    __syncthreads();
#pragma unroll
    for (int i = 0; i < 4; i++) {
        int nn = ty + i * 8;
        th[(size_t)(nb + nn) * DDIM + kb + tx] = __float2half_rn(t[tx][nn]);
    }
}

// ============================ HMMA GEMM (fp16 2-pass, fp32 acc) ==============
// BM=256, BN=128, BK=64, 256 threads, warp tile 64x64, 2 stages.
// C = (Ah + Al) @ Bh : A exact via hi/lo, B single fp16 (err ~1e-4).
// EPI 1: C = relu(A@W+b)+res (fp32). EPI 2: fp16 hi/lo out. EPI 3: fp16 hi out.
#define G_SST   144                      // smem row stride bytes (72 halves)
#define G_ATILE (256 * G_SST)            // 36864
#define G_BTILE (128 * G_SST)            // 18432
#define G_STAGE (2 * G_ATILE + G_BTILE)  // 92160 : Ah, Al, Bh
#define GSMEM   (2 * G_STAGE)            // 184320

template <int EPI>
__global__ __launch_bounds__(256)
void gemm_mma(const __half* __restrict__ Ah_, const __half* __restrict__ Al_,
              const __half* __restrict__ Bh_,
              const float* __restrict__ bias, const float* __restrict__ res,
              float* __restrict__ C,
              __half* __restrict__ Ch, __half* __restrict__ Cl)
{
    extern __shared__ __align__(128) char gsm[];
    const uint32_t sb = smem_u32(gsm);
    const int tid = threadIdx.x, lid = tid & 31, wid = tid >> 5;
    const int wm = (wid & 3) * 64, wn = (wid >> 2) * 64;
    const int bm = blockIdx.y * 256, bn = blockIdx.x * 128;

    const uint32_t aoff = (uint32_t)(wm + (lid & 15)) * G_SST + (((lid >> 4) & 1) * 16);
    const uint32_t boff = (uint32_t)(((lid >> 4) & 1) * 8 + (lid & 7)) * G_SST
                        + (((lid >> 3) & 1) * 16);

    float acc[4][8][4];
#pragma unroll
    for (int i = 0; i < 4; i++)
#pragma unroll
        for (int j = 0; j < 8; j++)
#pragma unroll
            for (int e = 0; e < 4; e++) acc[i][j][e] = 0.0f;

    auto LOAD = [&](int stg, int k0) {
        const uint32_t s = sb + (uint32_t)stg * G_STAGE;
#pragma unroll
        for (int t = 0; t < 8; t++) {           // A: 2048 rows*segs per tensor
            int idx = tid + t * 256;
            int r = idx >> 3, sg = idx & 7;
            uint32_t so = (uint32_t)r * G_SST + sg * 16;
            size_t go = (size_t)(bm + r) * DDIM + k0 + sg * 8;
            cp16(s + so,           Ah_ + go);
            cp16(s + G_ATILE + so, Al_ + go);
        }
#pragma unroll
        for (int t = 0; t < 4; t++) {           // Bh: 1024
            int idx = tid + t * 256;
            int r = idx >> 3, sg = idx & 7;
            uint32_t so = (uint32_t)r * G_SST + sg * 16;
            size_t go = (size_t)(bn + r) * DDIM + k0 + sg * 8;
            cp16(s + 2 * G_ATILE + so, Bh_ + go);
        }
    };

    LOAD(0, 0);
    CP_COMMIT();

    for (int c = 0; c < 16; c++) {
        if (c + 1 < 16) { LOAD((c + 1) & 1, (c + 1) * 64); CP_COMMIT(); CP_WAIT(1); }
        else            { CP_WAIT(0); }
        __syncthreads();
        const uint32_t st = sb + (uint32_t)(c & 1) * G_STAGE;

#pragma unroll
        for (int s = 0; s < 4; s++) {
            const uint32_t ks = s * 32;          // 16 halves per k-step
            uint32_t AH[4][4], AL[4][4];
#pragma unroll
            for (int i = 0; i < 4; i++) {
                ldsm4(AH[i], st + aoff + (uint32_t)(i * 16) * G_SST + ks);
                ldsm4(AL[i], st + G_ATILE + aoff + (uint32_t)(i * 16) * G_SST + ks);
            }
#pragma unroll
            for (int g = 0; g < 4; g++) {
                uint32_t BH[4];
                ldsm4(BH, st + 2 * G_ATILE + (uint32_t)(wn + g * 16) * G_SST + boff + ks);
#pragma unroll
                for (int i = 0; i < 4; i++) {
                    mma16816(acc[i][2 * g],     AH[i], &BH[0]);
                    mma16816(acc[i][2 * g + 1], AH[i], &BH[2]);
                }
#pragma unroll
                for (int i = 0; i < 4; i++) {
                    mma16816(acc[i][2 * g],     AL[i], &BH[0]);
                    mma16816(acc[i][2 * g + 1], AL[i], &BH[2]);
                }
            }
        }
        __syncthreads();
    }

    // epilogue
    const int gr = lid >> 2, gc = (lid & 3) * 2;
#pragma unroll
    for (int i = 0; i < 4; i++) {
        const int r0 = bm + wm + i * 16 + gr;
        const int r1 = r0 + 8;
#pragma unroll
        for (int j = 0; j < 8; j++) {
            const int col = bn + wn + j * 8 + gc;
            const float bx = bias[col], by = bias[col + 1];
            float v0 = acc[i][j][0] + bx, v1 = acc[i][j][1] + by;
            float v2 = acc[i][j][2] + bx, v3 = acc[i][j][3] + by;
            if (EPI == 2) {
                uint32_t h01, l01, h23, l23;
                hi_lo_pack(v0, v1, h01, l01);
                hi_lo_pack(v2, v3, h23, l23);
                *(uint32_t*)(Ch + (size_t)r0 * DDIM + col) = h01;
                *(uint32_t*)(Cl + (size_t)r0 * DDIM + col) = l01;
                *(uint32_t*)(Ch + (size_t)r1 * DDIM + col) = h23;
                *(uint32_t*)(Cl + (size_t)r1 * DDIM + col) = l23;
            } else if (EPI == 3) {
                *(uint32_t*)(Ch + (size_t)r0 * DDIM + col) = hi_pack(v0, v1);
                *(uint32_t*)(Ch + (size_t)r1 * DDIM + col) = hi_pack(v2, v3);
            } else {
                if (EPI == 1) {
                    const float* rp0 = res + (size_t)r0 * DDIM + col;
                    const float* rp1 = res + (size_t)r1 * DDIM + col;
                    v0 = fmaxf(v0, 0.0f) + rp0[0];
                    v1 = fmaxf(v1, 0.0f) + rp0[1];
                    v2 = fmaxf(v2, 0.0f) + rp1[0];
                    v3 = fmaxf(v3, 0.0f) + rp1[1];
                }
                *(float2*)(C + (size_t)r0 * DDIM + col) = make_float2(v0, v1);
                *(float2*)(C + (size_t)r1 * DDIM + col) = make_float2(v2, v3);
            }
        }
    }
}

// ============================ HMMA flash attention (fp16 2-pass) =============
// CTA = 128 q-rows of one (b,h), 256 threads (8 warps x 16 rows).
// K,V single fp16; Q and P hi/lo 2-pass. K/V chunks of 128, 2-stage.
#define AST_B   144
#define ATILE_B (128 * AST_B)              // 18432
#define ASMEM   (6 * ATILE_B)              // 110592: Qh,Ql + 2 stages x (Kh,Vh)

__global__ __launch_bounds__(256, 1)
void attn_mma(const __half* __restrict__ Qh_g, const __half* __restrict__ Ql_g,
              const __half* __restrict__ Kh_g, const __half* __restrict__ Vh_g,
              float* __restrict__ O)
{
    extern __shared__ __align__(128) char asm_[];
    const uint32_t sb = smem_u32(asm_);
    const int tid = threadIdx.x, lid = tid & 31, wid = tid >> 5;
    const int bh = blockIdx.y, b = bh >> 4, h = bh & 15;
    const int q0 = blockIdx.x * 128;

    const size_t qbase = (size_t)(b * NSEQ + q0) * DDIM + h * DHEAD;
    const size_t kbase = (size_t)(b * NSEQ) * DDIM + h * DHEAD;

    const uint32_t sQh = sb, sQl = sb + ATILE_B;
    const uint32_t kv0 = sb + 2 * ATILE_B;
    const uint32_t aoff = (uint32_t)(16 * wid + (lid & 15)) * AST_B + ((lid >> 4) & 1) * 16;
    const uint32_t boff = (uint32_t)(((lid >> 4) & 1) * 8 + (lid & 7)) * AST_B
                        + ((lid >> 3) & 1) * 16;
    const uint32_t voff = (uint32_t)(lid & 15) * AST_B + ((lid >> 4) & 1) * 16;

    auto loadKV = [&](int kt, int st) {
        const uint32_t base = kv0 + (uint32_t)st * (2 * ATILE_B);
        const size_t gk = kbase + (size_t)(kt * 128) * DDIM;
        for (int i = tid; i < 1024; i += 256) {
            int r = i >> 3, sg = i & 7;
            uint32_t so = (uint32_t)r * AST_B + sg * 16;
            size_t go = gk + (size_t)r * DDIM + sg * 8;
            cp16(base + so,           Kh_g + go);
            cp16(base + ATILE_B + so, Vh_g + go);
        }
    };

    for (int i = tid; i < 1024; i += 256) {
        int r = i >> 3, sg = i & 7;
        uint32_t so = (uint32_t)r * AST_B + sg * 16;
        size_t go = qbase + (size_t)r * DDIM + sg * 8;
        cp16(sQh + so, Qh_g + go);
        cp16(sQl + so, Ql_g + go);
    }
    loadKV(0, 0);
    CP_COMMIT();
    loadKV(1, 1);
    CP_COMMIT();
    CP_WAIT(1);
    __syncthreads();

    float m0 = -1e30f, m1 = -1e30f, l0v = 0.0f, l1v = 0.0f;
    float ov[8][4];
#pragma unroll
    for (int j = 0; j < 8; j++)
#pragma unroll
        for (int e = 0; e < 4; e++) ov[j][e] = 0.0f;

    for (int kt = 0; kt < 8; kt++) {
        const uint32_t kvb = kv0 + (uint32_t)(kt & 1) * (2 * ATILE_B);

        float sacc[16][4];
#pragma unroll
        for (int t = 0; t < 16; t++)
#pragma unroll
            for (int e = 0; e < 4; e++) sacc[t][e] = 0.0f;

#pragma unroll
        for (int kk = 0; kk < 4; kk++) {
            uint32_t QH[4], QL[4];
            ldsm4(QH, sQh + aoff + kk * 32);
            ldsm4(QL, sQl + aoff + kk * 32);
#pragma unroll
            for (int n = 0; n < 8; n++) {
                uint32_t KB[4];
                ldsm4(KB, kvb + boff + (uint32_t)n * (16 * AST_B) + kk * 32);
                mma16816(sacc[2 * n],     QH, &KB[0]);
                mma16816(sacc[2 * n + 1], QH, &KB[2]);
                mma16816(sacc[2 * n],     QL, &KB[0]);
                mma16816(sacc[2 * n + 1], QL, &KB[2]);
            }
        }

        const float scale = 0.03125f;
        float mx0 = -1e30f, mx1 = -1e30f;
#pragma unroll
        for (int t = 0; t < 16; t++) {
            sacc[t][0] *= scale; sacc[t][1] *= scale;
            sacc[t][2] *= scale; sacc[t][3] *= scale;
            mx0 = fmaxf(mx0, fmaxf(sacc[t][0], sacc[t][1]));
            mx1 = fmaxf(mx1, fmaxf(sacc[t][2], sacc[t][3]));
        }
        mx0 = fmaxf(mx0, __shfl_xor_sync(0xffffffffu, mx0, 1));
        mx0 = fmaxf(mx0, __shfl_xor_sync(0xffffffffu, mx0, 2));
        mx1 = fmaxf(mx1, __shfl_xor_sync(0xffffffffu, mx1, 1));
        mx1 = fmaxf(mx1, __shfl_xor_sync(0xffffffffu, mx1, 2));
        const float mn0 = fmaxf(m0, mx0), mn1 = fmaxf(m1, mx1);
        const float a0 = __expf(m0 - mn0), a1 = __expf(m1 - mn1);
        float rs0 = 0.0f, rs1 = 0.0f;
#pragma unroll
        for (int t = 0; t < 16; t++) {
            float e0 = __expf(sacc[t][0] - mn0);
            float e1 = __expf(sacc[t][1] - mn0);
            float e2 = __expf(sacc[t][2] - mn1);
            float e3 = __expf(sacc[t][3] - mn1);
            sacc[t][0] = e0; sacc[t][1] = e1; sacc[t][2] = e2; sacc[t][3] = e3;
            rs0 += e0 + e1; rs1 += e2 + e3;
        }
        rs0 += __shfl_xor_sync(0xffffffffu, rs0, 1);
        rs0 += __shfl_xor_sync(0xffffffffu, rs0, 2);
        rs1 += __shfl_xor_sync(0xffffffffu, rs1, 1);
        rs1 += __shfl_xor_sync(0xffffffffu, rs1, 2);
        l0v = l0v * a0 + rs0;
        l1v = l1v * a1 + rs1;
        m0 = mn0; m1 = mn1;
#pragma unroll
        for (int j = 0; j < 8; j++) {
            ov[j][0] *= a0; ov[j][1] *= a0;
            ov[j][2] *= a1; ov[j][3] *= a1;
        }

        const uint32_t sVh = kvb + ATILE_B;
#pragma unroll
        for (int t = 0; t < 8; t++) {
            uint32_t aPh[4], aPl[4];
            hi_lo_pack(sacc[2 * t][0],     sacc[2 * t][1],     aPh[0], aPl[0]);
            hi_lo_pack(sacc[2 * t][2],     sacc[2 * t][3],     aPh[1], aPl[1]);
            hi_lo_pack(sacc[2 * t + 1][0], sacc[2 * t + 1][1], aPh[2], aPl[2]);
            hi_lo_pack(sacc[2 * t + 1][2], sacc[2 * t + 1][3], aPh[3], aPl[3]);
#pragma unroll
            for (int nv = 0; nv < 4; nv++) {
                uint32_t VB[4];
                ldsm4t(VB, sVh + voff + (uint32_t)t * (16 * AST_B) + nv * 32);
                mma16816(ov[2 * nv],     aPh, &VB[0]);
                mma16816(ov[2 * nv + 1], aPh, &VB[2]);
                mma16816(ov[2 * nv],     aPl, &VB[0]);
                mma16816(ov[2 * nv + 1], aPl, &VB[2]);
            }
        }

        __syncthreads();
        if (kt + 2 < 8) {
            loadKV(kt + 2, kt & 1);
            CP_COMMIT();
            CP_WAIT(1);
            __syncthreads();
        } else if (kt + 1 < 8) {
            CP_WAIT(0);
            __syncthreads();
        }
    }

    const float inv0 = 1.0f / l0v, inv1 = 1.0f / l1v;
    const int gr = lid >> 2, gc = (lid & 3) * 2;
    float* op0 = O + (size_t)(b * NSEQ + q0 + 16 * wid + gr) * DDIM + h * DHEAD;
    float* op1 = op0 + 8 * DDIM;
#pragma unroll
    for (int j = 0; j < 8; j++) {
        *(float2*)(op0 + j * 8 + gc) = make_float2(ov[j][0] * inv0, ov[j][1] * inv0);
        *(float2*)(op1 + j * 8 + gc) = make_float2(ov[j][2] * inv1, ov[j][3] * inv1);
    }
}

// ============================ LayerNorm (+ optional fp16 split out) ==========
__global__ __launch_bounds__(256)
void ln_kernel(const float* __restrict__ A, const float* __restrict__ R,
               const float* __restrict__ gamma, const float* __restrict__ beta,
               float* __restrict__ out,
               __half* __restrict__ hi, __half* __restrict__ lo)
{
    const int row = blockIdx.x;
    const int tid = threadIdx.x;
    const size_t base = (size_t)row * DDIM + tid * 4;

    float4 v = *(const float4*)(A + base);
    if (R != nullptr) {
        float4 r = *(const float4*)(R + base);
        v.x += r.x; v.y += r.y; v.z += r.z; v.w += r.w;
    }

    __shared__ float red1[8];
    __shared__ float red2[8];

    float s = v.x + v.y + v.z + v.w;
#pragma unroll
    for (int off = 16; off > 0; off >>= 1) s += __shfl_xor_sync(0xffffffffu, s, off);
    if ((tid & 31) == 0) red1[tid >> 5] = s;
    __syncthreads();
    float tot = 0.0f;
#pragma unroll
    for (int k = 0; k < 8; k++) tot += red1[k];
    float mean = tot * (1.0f / 1024.0f);

    float d0 = v.x - mean, d1 = v.y - mean, d2 = v.z - mean, d3 = v.w - mean;
    float sq = d0 * d0 + d1 * d1 + d2 * d2 + d3 * d3;
#pragma unroll
    for (int off = 16; off > 0; off >>= 1) sq += __shfl_xor_sync(0xffffffffu, sq, off);
    if ((tid & 31) == 0) red2[tid >> 5] = sq;
    __syncthreads();
    float vtot = 0.0f;
#pragma unroll
    for (int k = 0; k < 8; k++) vtot += red2[k];
    float rstd = rsqrtf(vtot * (1.0f / 1024.0f) + 1e-6f);

    float4 g4 = *(const float4*)(gamma + tid * 4);
    float4 b4 = *(const float4*)(beta  + tid * 4);
    float4 o4 = make_float4(d0 * rstd * g4.x + b4.x,
                            d1 * rstd * g4.y + b4.y,
                            d2 * rstd * g4.z + b4.z,
                            d3 * rstd * g4.w + b4.w);
    *(float4*)(out + base) = o4;

    if (hi != nullptr) {
        uint32_t h01, l01, h23, l23;
        hi_lo_pack(o4.x, o4.y, h01, l01);
        hi_lo_pack(o4.z, o4.w, h23, l23);
        uint2 hw, lw;
        hw.x = h01; hw.y = h23;
        lw.x = l01; lw.y = l23;
        *(uint2*)(hi + base) = hw;
        *(uint2*)(lo + base) = lw;
    }
}

// ============================ host launch ====================================
extern "C" void kernel_launch(void* const* d_in, const int* in_sizes, int n_in,
                              void* d_out, int out_size)
{
    (void)in_sizes; (void)n_in; (void)out_size;
    const float* x  = (const float*)d_in[0];
    const float* y  = (const float*)d_in[1];
    const float* Wq = (const float*)d_in[2];
    const float* bq = (const float*)d_in[3];
    const float* Wk = (const float*)d_in[4];
    const float* bk = (const float*)d_in[5];
    const float* Wv = (const float*)d_in[6];
    const float* bv = (const float*)d_in[7];
    const float* Wf = (const float*)d_in[8];
    const float* bf = (const float*)d_in[9];
    const float* g1 = (const float*)d_in[10];
    const float* b1 = (const float*)d_in[11];
    const float* g2 = (const float*)d_in[12];
    const float* b2 = (const float*)d_in[13];
    float* out = (float*)d_out;

    float *pao, *ph1, *pt;
    cudaGetSymbolAddress((void**)&pao, g_ao);
    cudaGetSymbolAddress((void**)&ph1, g_h1);
    cudaGetSymbolAddress((void**)&pt,  g_t);

    void *paxh, *paxl, *payh, *payl, *pwth;
    void *pqh, *pql, *pkh, *pvh;
    cudaGetSymbolAddress(&paxh, g_axh);
    cudaGetSymbolAddress(&paxl, g_axl);
    cudaGetSymbolAddress(&payh, g_ayh);
    cudaGetSymbolAddress(&payl, g_ayl);
    cudaGetSymbolAddress(&pwth, g_wth);
    cudaGetSymbolAddress(&pqh, g_qh);
    cudaGetSymbolAddress(&pql, g_ql);
    cudaGetSymbolAddress(&pkh, g_kh);
    cudaGetSymbolAddress(&pvh, g_vh);

    __half* axh = (__half*)paxh;
    __half* axl = (__half*)paxl;
    __half* ayh = (__half*)payh;
    __half* ayl = (__half*)payl;
    __half* wth = (__half*)pwth;
    __half* qh = (__half*)pqh;
    __half* ql = (__half*)pql;
    __half* kh = (__half*)pkh;
    __half* vh = (__half*)pvh;
    const size_t WSZ = (size_t)DDIM * DDIM;

    cudaFuncSetAttribute(gemm_mma<1>, cudaFuncAttributeMaxDynamicSharedMemorySize, GSMEM);
    cudaFuncSetAttribute(gemm_mma<2>, cudaFuncAttributeMaxDynamicSharedMemorySize, GSMEM);
    cudaFuncSetAttribute(gemm_mma<3>, cudaFuncAttributeMaxDynamicSharedMemorySize, GSMEM);
    cudaFuncSetAttribute(attn_mma, cudaFuncAttributeMaxDynamicSharedMemorySize, ASMEM);

    dim3 sgrid((MROWS * DDIM) / 4 / 256, 1, 2);        // (8192,1,2)
    dim3 tgrid(32, 32, 4), tblk(256);
    dim3 ggrid(DDIM / 128, MROWS / 256);                // (8, 32) = 256 CTAs

    // prep: splits + weight transposes (merged launches)
    split2_kernel<<<sgrid, 256>>>(x, y, axh, axl, ayh, ayl);
    tsplit4_kernel<<<tgrid, tblk>>>(Wq, Wk, Wv, Wf, wth);

    // projections: Q -> hi/lo, K/V -> hi only
    gemm_mma<2><<<ggrid, 256, GSMEM>>>(axh, axl, wth + 0 * WSZ, bq, nullptr, nullptr, qh, ql);
    gemm_mma<3><<<ggrid, 256, GSMEM>>>(ayh, ayl, wth + 1 * WSZ, bk, nullptr, nullptr, kh, nullptr);
    gemm_mma<3><<<ggrid, 256, GSMEM>>>(ayh, ayl, wth + 2 * WSZ, bv, nullptr, nullptr, vh, nullptr);

    // attention (tensor cores, fp16 2-pass)
    attn_mma<<<dim3(NSEQ / 128, BB * NH), 256, ASMEM>>>(qh, ql, kh, vh, pao);

    // LN1(x + attn) -> fp32 h1 AND fp16 hi/lo split
    ln_kernel<<<MROWS, 256>>>(x, pao, g1, b1, ph1, axh, axl);

    // FF: t = relu(h1 @ Wf + bf) + h1
    gemm_mma<1><<<ggrid, 256, GSMEM>>>(axh, axl, wth + 3 * WSZ, bf, ph1, pt, nullptr, nullptr);

    // LN2
    ln_kernel<<<MROWS, 256>>>(pt, nullptr, g2, b2, out, nullptr, nullptr);
}

// round 12
// speedup vs baseline: 24.6643x; 1.6026x over previous
#include <cuda_runtime.h>
#include <cuda_fp16.h>
#include <math.h>
#include <stdint.h>

// Problem constants
#define BB    8
#define NSEQ  1024
#define DDIM  1024
#define NH    16
#define DHEAD 64
#define MROWS (BB * NSEQ)   // 8192

// ============================ PTX helpers ====================================
__device__ __forceinline__ uint32_t smem_u32(const void* p) {
    uint32_t a;
    asm("{ .reg .u64 t; cvta.to.shared.u64 t, %1; cvt.u32.u64 %0, t; }" : "=r"(a) : "l"(p));
    return a;
}
__device__ __forceinline__ void cp16(uint32_t d, const void* s) {
    asm volatile("cp.async.cg.shared.global [%0], [%1], 16;" :: "r"(d), "l"(s) : "memory");
}
#define CP_COMMIT() asm volatile("cp.async.commit_group;" ::: "memory")
#define CP_WAIT(n)  asm volatile("cp.async.wait_group %0;" :: "n"(n) : "memory")

__device__ __forceinline__ void ldsm4(uint32_t* r, uint32_t a) {
    asm volatile("ldmatrix.sync.aligned.m8n8.x4.shared.b16 {%0,%1,%2,%3}, [%4];"
        : "=r"(r[0]), "=r"(r[1]), "=r"(r[2]), "=r"(r[3]) : "r"(a));
}
__device__ __forceinline__ void ldsm4t(uint32_t* r, uint32_t a) {
    asm volatile("ldmatrix.sync.aligned.m8n8.x4.trans.shared.b16 {%0,%1,%2,%3}, [%4];"
        : "=r"(r[0]), "=r"(r[1]), "=r"(r[2]), "=r"(r[3]) : "r"(a));
}
// fp16 in, fp32 accumulate
__device__ __forceinline__ void mma16816(float* c, const uint32_t* a, const uint32_t* b) {
    asm volatile("mma.sync.aligned.m16n8k16.row.col.f32.f16.f16.f32 "
        "{%0,%1,%2,%3}, {%4,%5,%6,%7}, {%8,%9}, {%0,%1,%2,%3};"
        : "+f"(c[0]), "+f"(c[1]), "+f"(c[2]), "+f"(c[3])
        : "r"(a[0]), "r"(a[1]), "r"(a[2]), "r"(a[3]), "r"(b[0]), "r"(b[1]));
}
__device__ __forceinline__ uint32_t hi_pack(float x, float y) {
    __half2 hv = __halves2half2(__float2half_rn(x), __float2half_rn(y));
    return *(uint32_t*)&hv;
}

// ============================ scratch buffers ================================
__device__ float g_ao[(size_t)MROWS * DDIM];
__device__ float g_h1[(size_t)MROWS * DDIM];
__device__ float g_t [(size_t)MROWS * DDIM];

__device__ __align__(1024) __half g_axh[(size_t)MROWS * DDIM];   // x / h1 fp16
__device__ __align__(1024) __half g_ayh[(size_t)MROWS * DDIM];   // y fp16
__device__ __align__(1024) __half g_wth[4][(size_t)DDIM * DDIM]; // weights^T fp16
__device__ __align__(1024) __half g_qh[(size_t)MROWS * DDIM];
__device__ __align__(1024) __half g_kh[(size_t)MROWS * DDIM];
__device__ __align__(1024) __half g_vh[(size_t)MROWS * DDIM];

// ============================ convert / transpose (merged launches) ==========
// z=0: convert x ; z=1: convert y
__global__ __launch_bounds__(256)
void conv2_kernel(const float* __restrict__ in0, const float* __restrict__ in1,
                  __half* __restrict__ o0, __half* __restrict__ o1)
{
    const float* in = blockIdx.z ? in1 : in0;
    __half* o = blockIdx.z ? o1 : o0;
    int i = blockIdx.x * 256 + threadIdx.x;
    float4 v = ((const float4*)in)[i];
    uint2 hw;
    hw.x = hi_pack(v.x, v.y);
    hw.y = hi_pack(v.z, v.w);
    ((uint2*)o)[i] = hw;
}

// 4 weights transposed in one launch (z selects weight); fp16
__global__ __launch_bounds__(256)
void tsplit4_kernel(const float* __restrict__ W0, const float* __restrict__ W1,
                    const float* __restrict__ W2, const float* __restrict__ W3,
                    __half* __restrict__ thb)
{
    const int w = blockIdx.z;
    const float* W = (w == 0) ? W0 : (w == 1) ? W1 : (w == 2) ? W2 : W3;
    __half* th = thb + (size_t)w * DDIM * DDIM;

    __shared__ float t[32][33];
    const int tx = threadIdx.x & 31;
    const int ty = threadIdx.x >> 5;
    const int kb = blockIdx.y * 32;
    const int nb = blockIdx.x * 32;
#pragma unroll
    for (int i = 0; i < 4; i++) {
        int kk = ty + i * 8;
        t[kk][tx] = W[(size_t)(kb + kk) * DDIM + nb + tx];
    }
    __syncthreads();
#pragma unroll
    for (int i = 0; i < 4; i++) {
        int nn = ty + i * 8;
        th[(size_t)(nb + nn) * DDIM + kb + tx] = __float2half_rn(t[tx][nn]);
    }
}

// ============================ HMMA GEMM (fp16 1-pass, fp32 acc) ==============
// BM=256, BN=128, BK=64, 256 threads, warp tile 64x64, 2 stages.
// EPI 1: C = relu(A@W+b)+res (fp32). EPI 3: fp16 out.
#define G_SST   144                      // smem row stride bytes (72 halves)
#define G_ATILE (256 * G_SST)            // 36864
#define G_BTILE (128 * G_SST)            // 18432
#define G_STAGE (G_ATILE + G_BTILE)      // 55296 : A, B
#define GSMEM   (2 * G_STAGE)            // 110592

template <int EPI>
__global__ __launch_bounds__(256)
void gemm_mma(const __half* __restrict__ A_, const __half* __restrict__ B_,
              const float* __restrict__ bias, const float* __restrict__ res,
              float* __restrict__ C, __half* __restrict__ Ch)
{
    extern __shared__ __align__(128) char gsm[];
    const uint32_t sb = smem_u32(gsm);
    const int tid = threadIdx.x, lid = tid & 31, wid = tid >> 5;
    const int wm = (wid & 3) * 64, wn = (wid >> 2) * 64;
    const int bm = blockIdx.y * 256, bn = blockIdx.x * 128;

    const uint32_t aoff = (uint32_t)(wm + (lid & 15)) * G_SST + (((lid >> 4) & 1) * 16);
    const uint32_t boff = (uint32_t)(((lid >> 4) & 1) * 8 + (lid & 7)) * G_SST
                        + (((lid >> 3) & 1) * 16);

    float acc[4][8][4];
#pragma unroll
    for (int i = 0; i < 4; i++)
#pragma unroll
        for (int j = 0; j < 8; j++)
#pragma unroll
            for (int e = 0; e < 4; e++) acc[i][j][e] = 0.0f;

    auto LOAD = [&](int stg, int k0) {
        const uint32_t s = sb + (uint32_t)stg * G_STAGE;
#pragma unroll
        for (int t = 0; t < 8; t++) {           // A: 2048 cp16
            int idx = tid + t * 256;
            int r = idx >> 3, sg = idx & 7;
            uint32_t so = (uint32_t)r * G_SST + sg * 16;
            size_t go = (size_t)(bm + r) * DDIM + k0 + sg * 8;
            cp16(s + so, A_ + go);
        }
#pragma unroll
        for (int t = 0; t < 4; t++) {           // B: 1024 cp16
            int idx = tid + t * 256;
            int r = idx >> 3, sg = idx & 7;
            uint32_t so = (uint32_t)r * G_SST + sg * 16;
            size_t go = (size_t)(bn + r) * DDIM + k0 + sg * 8;
            cp16(s + G_ATILE + so, B_ + go);
        }
    };

    LOAD(0, 0);
    CP_COMMIT();

    for (int c = 0; c < 16; c++) {
        if (c + 1 < 16) { LOAD((c + 1) & 1, (c + 1) * 64); CP_COMMIT(); CP_WAIT(1); }
        else            { CP_WAIT(0); }
        __syncthreads();
        const uint32_t st = sb + (uint32_t)(c & 1) * G_STAGE;

#pragma unroll
        for (int s = 0; s < 4; s++) {
            const uint32_t ks = s * 32;          // 16 halves per k-step
            uint32_t AH[4][4];
#pragma unroll
            for (int i = 0; i < 4; i++)
                ldsm4(AH[i], st + aoff + (uint32_t)(i * 16) * G_SST + ks);
#pragma unroll
            for (int g = 0; g < 4; g++) {
                uint32_t BH[4];
                ldsm4(BH, st + G_ATILE + (uint32_t)(wn + g * 16) * G_SST + boff + ks);
#pragma unroll
                for (int i = 0; i < 4; i++) {
                    mma16816(acc[i][2 * g],     AH[i], &BH[0]);
                    mma16816(acc[i][2 * g + 1], AH[i], &BH[2]);
                }
            }
        }
        __syncthreads();
    }

    // epilogue
    const int gr = lid >> 2, gc = (lid & 3) * 2;
#pragma unroll
    for (int i = 0; i < 4; i++) {
        const int r0 = bm + wm + i * 16 + gr;
        const int r1 = r0 + 8;
#pragma unroll
        for (int j = 0; j < 8; j++) {
            const int col = bn + wn + j * 8 + gc;
            const float bx = bias[col], by = bias[col + 1];
            float v0 = acc[i][j][0] + bx, v1 = acc[i][j][1] + by;
            float v2 = acc[i][j][2] + bx, v3 = acc[i][j][3] + by;
            if (EPI == 3) {
                *(uint32_t*)(Ch + (size_t)r0 * DDIM + col) = hi_pack(v0, v1);
                *(uint32_t*)(Ch + (size_t)r1 * DDIM + col) = hi_pack(v2, v3);
            } else {
                if (EPI == 1) {
                    const float* rp0 = res + (size_t)r0 * DDIM + col;
                    const float* rp1 = res + (size_t)r1 * DDIM + col;
                    v0 = fmaxf(v0, 0.0f) + rp0[0];
                    v1 = fmaxf(v1, 0.0f) + rp0[1];
                    v2 = fmaxf(v2, 0.0f) + rp1[0];
                    v3 = fmaxf(v3, 0.0f) + rp1[1];
                }
                *(float2*)(C + (size_t)r0 * DDIM + col) = make_float2(v0, v1);
                *(float2*)(C + (size_t)r1 * DDIM + col) = make_float2(v2, v3);
            }
        }
    }
}

// ============================ HMMA flash attention (fp16 1-pass) =============
// CTA = 128 q-rows of one (b,h), 256 threads (8 warps x 16 rows).
// Q, K, V, P all single fp16; fp32 accum. K/V chunks of 128, 2-stage.
#define AST_B   144
#define ATILE_B (128 * AST_B)              // 18432
#define ASMEM   (5 * ATILE_B)              // 92160: Q + 2 stages x (K,V)

__global__ __launch_bounds__(256, 1)
void attn_mma(const __half* __restrict__ Q_g, const __half* __restrict__ K_g,
              const __half* __restrict__ V_g, float* __restrict__ O)
{
    extern __shared__ __align__(128) char asm_[];
    const uint32_t sb = smem_u32(asm_);
    const int tid = threadIdx.x, lid = tid & 31, wid = tid >> 5;
    const int bh = blockIdx.y, b = bh >> 4, h = bh & 15;
    const int q0 = blockIdx.x * 128;

    const size_t qbase = (size_t)(b * NSEQ + q0) * DDIM + h * DHEAD;
    const size_t kbase = (size_t)(b * NSEQ) * DDIM + h * DHEAD;

    const uint32_t sQ  = sb;
    const uint32_t kv0 = sb + ATILE_B;
    const uint32_t aoff = (uint32_t)(16 * wid + (lid & 15)) * AST_B + ((lid >> 4) & 1) * 16;
    const uint32_t boff = (uint32_t)(((lid >> 4) & 1) * 8 + (lid & 7)) * AST_B
                        + ((lid >> 3) & 1) * 16;
    const uint32_t voff = (uint32_t)(lid & 15) * AST_B + ((lid >> 4) & 1) * 16;

    auto loadKV = [&](int kt, int st) {
        const uint32_t base = kv0 + (uint32_t)st * (2 * ATILE_B);
        const size_t gk = kbase + (size_t)(kt * 128) * DDIM;
        for (int i = tid; i < 1024; i += 256) {
            int r = i >> 3, sg = i & 7;
            uint32_t so = (uint32_t)r * AST_B + sg * 16;
            size_t go = gk + (size_t)r * DDIM + sg * 8;
            cp16(base + so,           K_g + go);
            cp16(base + ATILE_B + so, V_g + go);
        }
    };

    for (int i = tid; i < 1024; i += 256) {
        int r = i >> 3, sg = i & 7;
        uint32_t so = (uint32_t)r * AST_B + sg * 16;
        cp16(sQ + so, Q_g + qbase + (size_t)r * DDIM + sg * 8);
    }
    loadKV(0, 0);
    CP_COMMIT();
    loadKV(1, 1);
    CP_COMMIT();
    CP_WAIT(1);
    __syncthreads();

    float m0 = -1e30f, m1 = -1e30f, l0v = 0.0f, l1v = 0.0f;
    float ov[8][4];
#pragma unroll
    for (int j = 0; j < 8; j++)
#pragma unroll
        for (int e = 0; e < 4; e++) ov[j][e] = 0.0f;

    for (int kt = 0; kt < 8; kt++) {
        const uint32_t kvb = kv0 + (uint32_t)(kt & 1) * (2 * ATILE_B);

        float sacc[16][4];
#pragma unroll
        for (int t = 0; t < 16; t++)
#pragma unroll
            for (int e = 0; e < 4; e++) sacc[t][e] = 0.0f;

#pragma unroll
        for (int kk = 0; kk < 4; kk++) {
            uint32_t QF[4];
            ldsm4(QF, sQ + aoff + kk * 32);
#pragma unroll
            for (int n = 0; n < 8; n++) {
                uint32_t KB[4];
                ldsm4(KB, kvb + boff + (uint32_t)n * (16 * AST_B) + kk * 32);
                mma16816(sacc[2 * n],     QF, &KB[0]);
                mma16816(sacc[2 * n + 1], QF, &KB[2]);
            }
        }

        const float scale = 0.03125f;
        float mx0 = -1e30f, mx1 = -1e30f;
#pragma unroll
        for (int t = 0; t < 16; t++) {
            sacc[t][0] *= scale; sacc[t][1] *= scale;
            sacc[t][2] *= scale; sacc[t][3] *= scale;
            mx0 = fmaxf(mx0, fmaxf(sacc[t][0], sacc[t][1]));
            mx1 = fmaxf(mx1, fmaxf(sacc[t][2], sacc[t][3]));
        }
        mx0 = fmaxf(mx0, __shfl_xor_sync(0xffffffffu, mx0, 1));
        mx0 = fmaxf(mx0, __shfl_xor_sync(0xffffffffu, mx0, 2));
        mx1 = fmaxf(mx1, __shfl_xor_sync(0xffffffffu, mx1, 1));
        mx1 = fmaxf(mx1, __shfl_xor_sync(0xffffffffu, mx1, 2));
        const float mn0 = fmaxf(m0, mx0), mn1 = fmaxf(m1, mx1);
        const float a0 = __expf(m0 - mn0), a1 = __expf(m1 - mn1);
        float rs0 = 0.0f, rs1 = 0.0f;
#pragma unroll
        for (int t = 0; t < 16; t++) {
            float e0 = __expf(sacc[t][0] - mn0);
            float e1 = __expf(sacc[t][1] - mn0);
            float e2 = __expf(sacc[t][2] - mn1);
            float e3 = __expf(sacc[t][3] - mn1);
            sacc[t][0] = e0; sacc[t][1] = e1; sacc[t][2] = e2; sacc[t][3] = e3;
            rs0 += e0 + e1; rs1 += e2 + e3;
        }
        rs0 += __shfl_xor_sync(0xffffffffu, rs0, 1);
        rs0 += __shfl_xor_sync(0xffffffffu, rs0, 2);
        rs1 += __shfl_xor_sync(0xffffffffu, rs1, 1);
        rs1 += __shfl_xor_sync(0xffffffffu, rs1, 2);
        l0v = l0v * a0 + rs0;
        l1v = l1v * a1 + rs1;
        m0 = mn0; m1 = mn1;
#pragma unroll
        for (int j = 0; j < 8; j++) {
            ov[j][0] *= a0; ov[j][1] *= a0;
            ov[j][2] *= a1; ov[j][3] *= a1;
        }

        const uint32_t sVh = kvb + ATILE_B;
#pragma unroll
        for (int t = 0; t < 8; t++) {
            uint32_t aP[4];
            aP[0] = hi_pack(sacc[2 * t][0],     sacc[2 * t][1]);
            aP[1] = hi_pack(sacc[2 * t][2],     sacc[2 * t][3]);
            aP[2] = hi_pack(sacc[2 * t + 1][0], sacc[2 * t + 1][1]);
            aP[3] = hi_pack(sacc[2 * t + 1][2], sacc[2 * t + 1][3]);
#pragma unroll
            for (int nv = 0; nv < 4; nv++) {
                uint32_t VB[4];
                ldsm4t(VB, sVh + voff + (uint32_t)t * (16 * AST_B) + nv * 32);
                mma16816(ov[2 * nv],     aP, &VB[0]);
                mma16816(ov[2 * nv + 1], aP, &VB[2]);
            }
        }

        __syncthreads();
        if (kt + 2 < 8) {
            loadKV(kt + 2, kt & 1);
            CP_COMMIT();
            CP_WAIT(1);
            __syncthreads();
        } else if (kt + 1 < 8) {
            CP_WAIT(0);
            __syncthreads();
        }
    }

    const float inv0 = 1.0f / l0v, inv1 = 1.0f / l1v;
    const int gr = lid >> 2, gc = (lid & 3) * 2;
    float* op0 = O + (size_t)(b * NSEQ + q0 + 16 * wid + gr) * DDIM + h * DHEAD;
    float* op1 = op0 + 8 * DDIM;
#pragma unroll
    for (int j = 0; j < 8; j++) {
        *(float2*)(op0 + j * 8 + gc) = make_float2(ov[j][0] * inv0, ov[j][1] * inv0);
        *(float2*)(op1 + j * 8 + gc) = make_float2(ov[j][2] * inv1, ov[j][3] * inv1);
    }
}

// ============================ LayerNorm (+ optional fp16 out) ================
__global__ __launch_bounds__(256)
void ln_kernel(const float* __restrict__ A, const float* __restrict__ R,
               const float* __restrict__ gamma, const float* __restrict__ beta,
               float* __restrict__ out, __half* __restrict__ hi)
{
    const int row = blockIdx.x;
    const int tid = threadIdx.x;
    const size_t base = (size_t)row * DDIM + tid * 4;

    float4 v = *(const float4*)(A + base);
    if (R != nullptr) {
        float4 r = *(const float4*)(R + base);
        v.x += r.x; v.y += r.y; v.z += r.z; v.w += r.w;
    }

    __shared__ float red1[8];
    __shared__ float red2[8];

    float s = v.x + v.y + v.z + v.w;
#pragma unroll
    for (int off = 16; off > 0; off >>= 1) s += __shfl_xor_sync(0xffffffffu, s, off);
    if ((tid & 31) == 0) red1[tid >> 5] = s;
    __syncthreads();
    float tot = 0.0f;
#pragma unroll
    for (int k = 0; k < 8; k++) tot += red1[k];
    float mean = tot * (1.0f / 1024.0f);

    float d0 = v.x - mean, d1 = v.y - mean, d2 = v.z - mean, d3 = v.w - mean;
    float sq = d0 * d0 + d1 * d1 + d2 * d2 + d3 * d3;
#pragma unroll
    for (int off = 16; off > 0; off >>= 1) sq += __shfl_xor_sync(0xffffffffu, sq, off);
    if ((tid & 31) == 0) red2[tid >> 5] = sq;
    __syncthreads();
    float vtot = 0.0f;
#pragma unroll
    for (int k = 0; k < 8; k++) vtot += red2[k];
    float rstd = rsqrtf(vtot * (1.0f / 1024.0f) + 1e-6f);

    float4 g4 = *(const float4*)(gamma + tid * 4);
    float4 b4 = *(const float4*)(beta  + tid * 4);
    float4 o4 = make_float4(d0 * rstd * g4.x + b4.x,
                            d1 * rstd * g4.y + b4.y,
                            d2 * rstd * g4.z + b4.z,
                            d3 * rstd * g4.w + b4.w);
    *(float4*)(out + base) = o4;

    if (hi != nullptr) {
        uint2 hw;
        hw.x = hi_pack(o4.x, o4.y);
        hw.y = hi_pack(o4.z, o4.w);
        *(uint2*)(hi + base) = hw;
    }
}

// ============================ host launch ====================================
extern "C" void kernel_launch(void* const* d_in, const int* in_sizes, int n_in,
                              void* d_out, int out_size)
{
    (void)in_sizes; (void)n_in; (void)out_size;
    const float* x  = (const float*)d_in[0];
    const float* y  = (const float*)d_in[1];
    const float* Wq = (const float*)d_in[2];
    const float* bq = (const float*)d_in[3];
    const float* Wk = (const float*)d_in[4];
    const float* bk = (const float*)d_in[5];
    const float* Wv = (const float*)d_in[6];
    const float* bv = (const float*)d_in[7];
    const float* Wf = (const float*)d_in[8];
    const float* bf = (const float*)d_in[9];
    const float* g1 = (const float*)d_in[10];
    const float* b1 = (const float*)d_in[11];
    const float* g2 = (const float*)d_in[12];
    const float* b2 = (const float*)d_in[13];
    float* out = (float*)d_out;

    float *pao, *ph1, *pt;
    cudaGetSymbolAddress((void**)&pao, g_ao);
    cudaGetSymbolAddress((void**)&ph1, g_h1);
    cudaGetSymbolAddress((void**)&pt,  g_t);

    void *paxh, *payh, *pwth, *pqh, *pkh, *pvh;
    cudaGetSymbolAddress(&paxh, g_axh);
    cudaGetSymbolAddress(&payh, g_ayh);
    cudaGetSymbolAddress(&pwth, g_wth);
    cudaGetSymbolAddress(&pqh, g_qh);
    cudaGetSymbolAddress(&pkh, g_kh);
    cudaGetSymbolAddress(&pvh, g_vh);

    __half* axh = (__half*)paxh;
    __half* ayh = (__half*)payh;
    __half* wth = (__half*)pwth;
    __half* qh = (__half*)pqh;
    __half* kh = (__half*)pkh;
    __half* vh = (__half*)pvh;
    const size_t WSZ = (size_t)DDIM * DDIM;

    cudaFuncSetAttribute(gemm_mma<1>, cudaFuncAttributeMaxDynamicSharedMemorySize, GSMEM);
    cudaFuncSetAttribute(gemm_mma<3>, cudaFuncAttributeMaxDynamicSharedMemorySize, GSMEM);
    cudaFuncSetAttribute(attn_mma, cudaFuncAttributeMaxDynamicSharedMemorySize, ASMEM);

    dim3 sgrid((MROWS * DDIM) / 4 / 256, 1, 2);        // (8192,1,2)
    dim3 tgrid(32, 32, 4), tblk(256);
    dim3 ggrid(DDIM / 128, MROWS / 256);                // (8, 32) = 256 CTAs

    // prep: fp16 converts + weight transposes (merged launches)
    conv2_kernel<<<sgrid, 256>>>(x, y, axh, ayh);
    tsplit4_kernel<<<tgrid, tblk>>>(Wq, Wk, Wv, Wf, wth);

    // projections -> fp16
    gemm_mma<3><<<ggrid, 256, GSMEM>>>(axh, wth + 0 * WSZ, bq, nullptr, nullptr, qh);
    gemm_mma<3><<<ggrid, 256, GSMEM>>>(ayh, wth + 1 * WSZ, bk, nullptr, nullptr, kh);
    gemm_mma<3><<<ggrid, 256, GSMEM>>>(ayh, wth + 2 * WSZ, bv, nullptr, nullptr, vh);

    // attention (fp16 1-pass)
    attn_mma<<<dim3(NSEQ / 128, BB * NH), 256, ASMEM>>>(qh, kh, vh, pao);

    // LN1(x + attn) -> fp32 h1 AND fp16 (reuses axh)
    ln_kernel<<<MROWS, 256>>>(x, pao, g1, b1, ph1, axh);

    // FF: t = relu(h1 @ Wf + bf) + h1
    gemm_mma<1><<<ggrid, 256, GSMEM>>>(axh, wth + 3 * WSZ, bf, ph1, pt, nullptr);

    // LN2
    ln_kernel<<<MROWS, 256>>>(pt, nullptr, g2, b2, out, nullptr);
}

// round 13
// speedup vs baseline: 25.5356x; 1.0353x over previous
#include <cuda_runtime.h>
#include <cuda_fp16.h>
#include <math.h>
#include <stdint.h>

// Problem constants
#define BB    8
#define NSEQ  1024
#define DDIM  1024
#define NH    16
#define DHEAD 64
#define MROWS (BB * NSEQ)   // 8192

// ============================ PTX helpers ====================================
__device__ __forceinline__ uint32_t smem_u32(const void* p) {
    uint32_t a;
    asm("{ .reg .u64 t; cvta.to.shared.u64 t, %1; cvt.u32.u64 %0, t; }" : "=r"(a) : "l"(p));
    return a;
}
__device__ __forceinline__ void cp16(uint32_t d, const void* s) {
    asm volatile("cp.async.cg.shared.global [%0], [%1], 16;" :: "r"(d), "l"(s) : "memory");
}
#define CP_COMMIT() asm volatile("cp.async.commit_group;" ::: "memory")
#define CP_WAIT(n)  asm volatile("cp.async.wait_group %0;" :: "n"(n) : "memory")

__device__ __forceinline__ void ldsm4(uint32_t* r, uint32_t a) {
    asm volatile("ldmatrix.sync.aligned.m8n8.x4.shared.b16 {%0,%1,%2,%3}, [%4];"
        : "=r"(r[0]), "=r"(r[1]), "=r"(r[2]), "=r"(r[3]) : "r"(a));
}
__device__ __forceinline__ void ldsm4t(uint32_t* r, uint32_t a) {
    asm volatile("ldmatrix.sync.aligned.m8n8.x4.trans.shared.b16 {%0,%1,%2,%3}, [%4];"
        : "=r"(r[0]), "=r"(r[1]), "=r"(r[2]), "=r"(r[3]) : "r"(a));
}
// fp16 in, fp32 accumulate
__device__ __forceinline__ void mma16816(float* c, const uint32_t* a, const uint32_t* b) {
    asm volatile("mma.sync.aligned.m16n8k16.row.col.f32.f16.f16.f32 "
        "{%0,%1,%2,%3}, {%4,%5,%6,%7}, {%8,%9}, {%0,%1,%2,%3};"
        : "+f"(c[0]), "+f"(c[1]), "+f"(c[2]), "+f"(c[3])
        : "r"(a[0]), "r"(a[1]), "r"(a[2]), "r"(a[3]), "r"(b[0]), "r"(b[1]));
}
__device__ __forceinline__ uint32_t hi_pack(float x, float y) {
    __half2 hv = __halves2half2(__float2half_rn(x), __float2half_rn(y));
    return *(uint32_t*)&hv;
}

// ============================ scratch buffers ================================
__device__ float g_ao[(size_t)MROWS * DDIM];
__device__ float g_h1[(size_t)MROWS * DDIM];
__device__ float g_t [(size_t)MROWS * DDIM];

__device__ __align__(1024) __half g_axh[(size_t)MROWS * DDIM];   // x / h1 fp16
__device__ __align__(1024) __half g_ayh[(size_t)MROWS * DDIM];   // y fp16
__device__ __align__(1024) __half g_wth[4][(size_t)DDIM * DDIM]; // weights^T fp16
__device__ __align__(1024) __half g_qh[(size_t)MROWS * DDIM];
__device__ __align__(1024) __half g_kh[(size_t)MROWS * DDIM];
__device__ __align__(1024) __half g_vh[(size_t)MROWS * DDIM];

// ============================ convert / transpose (merged launches) ==========
// z=0: convert x ; z=1: convert y
__global__ __launch_bounds__(256)
void conv2_kernel(const float* __restrict__ in0, const float* __restrict__ in1,
                  __half* __restrict__ o0, __half* __restrict__ o1)
{
    const float* in = blockIdx.z ? in1 : in0;
    __half* o = blockIdx.z ? o1 : o0;
    int i = blockIdx.x * 256 + threadIdx.x;
    float4 v = ((const float4*)in)[i];
    uint2 hw;
    hw.x = hi_pack(v.x, v.y);
    hw.y = hi_pack(v.z, v.w);
    ((uint2*)o)[i] = hw;
}

// 4 weights transposed in one launch (z selects weight); fp16
__global__ __launch_bounds__(256)
void tsplit4_kernel(const float* __restrict__ W0, const float* __restrict__ W1,
                    const float* __restrict__ W2, const float* __restrict__ W3,
                    __half* __restrict__ thb)
{
    const int w = blockIdx.z;
    const float* W = (w == 0) ? W0 : (w == 1) ? W1 : (w == 2) ? W2 : W3;
    __half* th = thb + (size_t)w * DDIM * DDIM;

    __shared__ float t[32][33];
    const int tx = threadIdx.x & 31;
    const int ty = threadIdx.x >> 5;
    const int kb = blockIdx.y * 32;
    const int nb = blockIdx.x * 32;
#pragma unroll
    for (int i = 0; i < 4; i++) {
        int kk = ty + i * 8;
        t[kk][tx] = W[(size_t)(kb + kk) * DDIM + nb + tx];
    }
    __syncthreads();
#pragma unroll
    for (int i = 0; i < 4; i++) {
        int nn = ty + i * 8;
        th[(size_t)(nb + nn) * DDIM + kb + tx] = __float2half_rn(t[tx][nn]);
    }
}

// ============================ HMMA GEMM (fp16 1-pass, fp32 acc) ==============
// BM=128, BN=128, BK=64, 256 threads, warp tile 64x32 (2m x 4n warps),
// 2 stages, 2 CTAs/SM (regs <=128, smem 72KB/CTA).
// EPI 1: C = relu(A@W+b)+res (fp32). EPI 3: fp16 out.
#define G_SST   144                      // smem row stride bytes (72 halves)
#define G_TILE  (128 * G_SST)            // 18432
#define G_STAGE (2 * G_TILE)             // 36864 : A, B
#define GSMEM   (2 * G_STAGE)            // 73728

template <int EPI>
__global__ __launch_bounds__(256, 2)
void gemm_mma(const __half* __restrict__ A_, const __half* __restrict__ B_,
              const float* __restrict__ bias, const float* __restrict__ res,
              float* __restrict__ C, __half* __restrict__ Ch)
{
    extern __shared__ __align__(128) char gsm[];
    const uint32_t sb = smem_u32(gsm);
    const int tid = threadIdx.x, lid = tid & 31, wid = tid >> 5;
    const int wm = (wid & 1) * 64, wn = (wid >> 1) * 32;
    const int bm = blockIdx.y * 128, bn = blockIdx.x * 128;

    const uint32_t aoff = (uint32_t)(wm + (lid & 15)) * G_SST + (((lid >> 4) & 1) * 16);
    const uint32_t boff = (uint32_t)(wn + ((lid >> 4) & 1) * 8 + (lid & 7)) * G_SST
                        + (((lid >> 3) & 1) * 16);

    float acc[4][4][4];
#pragma unroll
    for (int i = 0; i < 4; i++)
#pragma unroll
        for (int j = 0; j < 4; j++)
#pragma unroll
            for (int e = 0; e < 4; e++) acc[i][j][e] = 0.0f;

    auto LOAD = [&](int stg, int k0) {
        const uint32_t s = sb + (uint32_t)stg * G_STAGE;
#pragma unroll
        for (int t = 0; t < 4; t++) {           // A + B: 1024 cp16 each
            int idx = tid + t * 256;
            int r = idx >> 3, sg = idx & 7;
            uint32_t so = (uint32_t)r * G_SST + sg * 16;
            size_t goA = (size_t)(bm + r) * DDIM + k0 + sg * 8;
            size_t goB = (size_t)(bn + r) * DDIM + k0 + sg * 8;
            cp16(s + so,          A_ + goA);
            cp16(s + G_TILE + so, B_ + goB);
        }
    };

    LOAD(0, 0);
    CP_COMMIT();

    for (int c = 0; c < 16; c++) {
        if (c + 1 < 16) { LOAD((c + 1) & 1, (c + 1) * 64); CP_COMMIT(); CP_WAIT(1); }
        else            { CP_WAIT(0); }
        __syncthreads();
        const uint32_t st = sb + (uint32_t)(c & 1) * G_STAGE;

#pragma unroll
        for (int s = 0; s < 4; s++) {
            const uint32_t ks = s * 32;          // 16 halves per k-step
            uint32_t AH[4][4], B0[4], B1[4];
#pragma unroll
            for (int i = 0; i < 4; i++)
                ldsm4(AH[i], st + aoff + (uint32_t)(i * 16) * G_SST + ks);
            ldsm4(B0, st + G_TILE + boff + ks);
            ldsm4(B1, st + G_TILE + boff + (uint32_t)(16 * G_SST) + ks);
#pragma unroll
            for (int i = 0; i < 4; i++) {
                mma16816(acc[i][0], AH[i], &B0[0]);
                mma16816(acc[i][1], AH[i], &B0[2]);
                mma16816(acc[i][2], AH[i], &B1[0]);
                mma16816(acc[i][3], AH[i], &B1[2]);
            }
        }
        __syncthreads();
    }

    // epilogue
    const int gr = lid >> 2, gc = (lid & 3) * 2;
#pragma unroll
    for (int i = 0; i < 4; i++) {
        const int r0 = bm + wm + i * 16 + gr;
        const int r1 = r0 + 8;
#pragma unroll
        for (int j = 0; j < 4; j++) {
            const int col = bn + wn + j * 8 + gc;
            const float bx = bias[col], by = bias[col + 1];
            float v0 = acc[i][j][0] + bx, v1 = acc[i][j][1] + by;
            float v2 = acc[i][j][2] + bx, v3 = acc[i][j][3] + by;
            if (EPI == 3) {
                *(uint32_t*)(Ch + (size_t)r0 * DDIM + col) = hi_pack(v0, v1);
                *(uint32_t*)(Ch + (size_t)r1 * DDIM + col) = hi_pack(v2, v3);
            } else {
                if (EPI == 1) {
                    const float* rp0 = res + (size_t)r0 * DDIM + col;
                    const float* rp1 = res + (size_t)r1 * DDIM + col;
                    v0 = fmaxf(v0, 0.0f) + rp0[0];
                    v1 = fmaxf(v1, 0.0f) + rp0[1];
                    v2 = fmaxf(v2, 0.0f) + rp1[0];
                    v3 = fmaxf(v3, 0.0f) + rp1[1];
                }
                *(float2*)(C + (size_t)r0 * DDIM + col) = make_float2(v0, v1);
                *(float2*)(C + (size_t)r1 * DDIM + col) = make_float2(v2, v3);
            }
        }
    }
}

// ============================ HMMA flash attention (fp16 1-pass) =============
// CTA = 128 q-rows of one (b,h), 256 threads (8 warps x 16 rows).
// Q, K, V, P all single fp16; fp32 accum. K/V chunks of 128, 2-stage.
#define AST_B   144
#define ATILE_B (128 * AST_B)              // 18432
#define ASMEM   (5 * ATILE_B)              // 92160: Q + 2 stages x (K,V)

__global__ __launch_bounds__(256, 1)
void attn_mma(const __half* __restrict__ Q_g, const __half* __restrict__ K_g,
              const __half* __restrict__ V_g, float* __restrict__ O)
{
    extern __shared__ __align__(128) char asm_[];
    const uint32_t sb = smem_u32(asm_);
    const int tid = threadIdx.x, lid = tid & 31, wid = tid >> 5;
    const int bh = blockIdx.y, b = bh >> 4, h = bh & 15;
    const int q0 = blockIdx.x * 128;

    const size_t qbase = (size_t)(b * NSEQ + q0) * DDIM + h * DHEAD;
    const size_t kbase = (size_t)(b * NSEQ) * DDIM + h * DHEAD;

    const uint32_t sQ  = sb;
    const uint32_t kv0 = sb + ATILE_B;
    const uint32_t aoff = (uint32_t)(16 * wid + (lid & 15)) * AST_B + ((lid >> 4) & 1) * 16;
    const uint32_t boff = (uint32_t)(((lid >> 4) & 1) * 8 + (lid & 7)) * AST_B
                        + ((lid >> 3) & 1) * 16;
    const uint32_t voff = (uint32_t)(lid & 15) * AST_B + ((lid >> 4) & 1) * 16;

    auto loadKV = [&](int kt, int st) {
        const uint32_t base = kv0 + (uint32_t)st * (2 * ATILE_B);
        const size_t gk = kbase + (size_t)(kt * 128) * DDIM;
        for (int i = tid; i < 1024; i += 256) {
            int r = i >> 3, sg = i & 7;
            uint32_t so = (uint32_t)r * AST_B + sg * 16;
            size_t go = gk + (size_t)r * DDIM + sg * 8;
            cp16(base + so,           K_g + go);
            cp16(base + ATILE_B + so, V_g + go);
        }
    };

    for (int i = tid; i < 1024; i += 256) {
        int r = i >> 3, sg = i & 7;
        uint32_t so = (uint32_t)r * AST_B + sg * 16;
        cp16(sQ + so, Q_g + qbase + (size_t)r * DDIM + sg * 8);
    }
    loadKV(0, 0);
    CP_COMMIT();
    loadKV(1, 1);
    CP_COMMIT();
    CP_WAIT(1);
    __syncthreads();

    float m0 = -1e30f, m1 = -1e30f, l0v = 0.0f, l1v = 0.0f;
    float ov[8][4];
#pragma unroll
    for (int j = 0; j < 8; j++)
#pragma unroll
        for (int e = 0; e < 4; e++) ov[j][e] = 0.0f;

    for (int kt = 0; kt < 8; kt++) {
        const uint32_t kvb = kv0 + (uint32_t)(kt & 1) * (2 * ATILE_B);

        float sacc[16][4];
#pragma unroll
        for (int t = 0; t < 16; t++)
#pragma unroll
            for (int e = 0; e < 4; e++) sacc[t][e] = 0.0f;

#pragma unroll
        for (int kk = 0; kk < 4; kk++) {
            uint32_t QF[4];
            ldsm4(QF, sQ + aoff + kk * 32);
#pragma unroll
            for (int n = 0; n < 8; n++) {
                uint32_t KB[4];
                ldsm4(KB, kvb + boff + (uint32_t)n * (16 * AST_B) + kk * 32);
                mma16816(sacc[2 * n],     QF, &KB[0]);
                mma16816(sacc[2 * n + 1], QF, &KB[2]);
            }
        }

        const float scale = 0.03125f;
        float mx0 = -1e30f, mx1 = -1e30f;
#pragma unroll
        for (int t = 0; t < 16; t++) {
            sacc[t][0] *= scale; sacc[t][1] *= scale;
            sacc[t][2] *= scale; sacc[t][3] *= scale;
            mx0 = fmaxf(mx0, fmaxf(sacc[t][0], sacc[t][1]));
            mx1 = fmaxf(mx1, fmaxf(sacc[t][2], sacc[t][3]));
        }
        mx0 = fmaxf(mx0, __shfl_xor_sync(0xffffffffu, mx0, 1));
        mx0 = fmaxf(mx0, __shfl_xor_sync(0xffffffffu, mx0, 2));
        mx1 = fmaxf(mx1, __shfl_xor_sync(0xffffffffu, mx1, 1));
        mx1 = fmaxf(mx1, __shfl_xor_sync(0xffffffffu, mx1, 2));
        const float mn0 = fmaxf(m0, mx0), mn1 = fmaxf(m1, mx1);
        const float a0 = __expf(m0 - mn0), a1 = __expf(m1 - mn1);
        float rs0 = 0.0f, rs1 = 0.0f;
#pragma unroll
        for (int t = 0; t < 16; t++) {
            float e0 = __expf(sacc[t][0] - mn0);
            float e1 = __expf(sacc[t][1] - mn0);
            float e2 = __expf(sacc[t][2] - mn1);
            float e3 = __expf(sacc[t][3] - mn1);
            sacc[t][0] = e0; sacc[t][1] = e1; sacc[t][2] = e2; sacc[t][3] = e3;
            rs0 += e0 + e1; rs1 += e2 + e3;
        }
        rs0 += __shfl_xor_sync(0xffffffffu, rs0, 1);
        rs0 += __shfl_xor_sync(0xffffffffu, rs0, 2);
        rs1 += __shfl_xor_sync(0xffffffffu, rs1, 1);
        rs1 += __shfl_xor_sync(0xffffffffu, rs1, 2);
        l0v = l0v * a0 + rs0;
        l1v = l1v * a1 + rs1;
        m0 = mn0; m1 = mn1;
#pragma unroll
        for (int j = 0; j < 8; j++) {
            ov[j][0] *= a0; ov[j][1] *= a0;
            ov[j][2] *= a1; ov[j][3] *= a1;
        }

        const uint32_t sVh = kvb + ATILE_B;
#pragma unroll
        for (int t = 0; t < 8; t++) {
            uint32_t aP[4];
            aP[0] = hi_pack(sacc[2 * t][0],     sacc[2 * t][1]);
            aP[1] = hi_pack(sacc[2 * t][2],     sacc[2 * t][3]);
            aP[2] = hi_pack(sacc[2 * t + 1][0], sacc[2 * t + 1][1]);
            aP[3] = hi_pack(sacc[2 * t + 1][2], sacc[2 * t + 1][3]);
#pragma unroll
            for (int nv = 0; nv < 4; nv++) {
                uint32_t VB[4];
                ldsm4t(VB, sVh + voff + (uint32_t)t * (16 * AST_B) + nv * 32);
                mma16816(ov[2 * nv],     aP, &VB[0]);
                mma16816(ov[2 * nv + 1], aP, &VB[2]);
            }
        }

        __syncthreads();
        if (kt + 2 < 8) {
            loadKV(kt + 2, kt & 1);
            CP_COMMIT();
            CP_WAIT(1);
            __syncthreads();
        } else if (kt + 1 < 8) {
            CP_WAIT(0);
            __syncthreads();
        }
    }

    const float inv0 = 1.0f / l0v, inv1 = 1.0f / l1v;
    const int gr = lid >> 2, gc = (lid & 3) * 2;
    float* op0 = O + (size_t)(b * NSEQ + q0 + 16 * wid + gr) * DDIM + h * DHEAD;
    float* op1 = op0 + 8 * DDIM;
#pragma unroll
    for (int j = 0; j < 8; j++) {
        *(float2*)(op0 + j * 8 + gc) = make_float2(ov[j][0] * inv0, ov[j][1] * inv0);
        *(float2*)(op1 + j * 8 + gc) = make_float2(ov[j][2] * inv1, ov[j][3] * inv1);
    }
}

// ============================ LayerNorm (+ optional fp16 out) ================
__global__ __launch_bounds__(256)
void ln_kernel(const float* __restrict__ A, const float* __restrict__ R,
               const float* __restrict__ gamma, const float* __restrict__ beta,
               float* __restrict__ out, __half* __restrict__ hi)
{
    const int row = blockIdx.x;
    const int tid = threadIdx.x;
    const size_t base = (size_t)row * DDIM + tid * 4;

    float4 v = *(const float4*)(A + base);
    if (R != nullptr) {
        float4 r = *(const float4*)(R + base);
        v.x += r.x; v.y += r.y; v.z += r.z; v.w += r.w;
    }

    __shared__ float red1[8];
    __shared__ float red2[8];

    float s = v.x + v.y + v.z + v.w;
#pragma unroll
    for (int off = 16; off > 0; off >>= 1) s += __shfl_xor_sync(0xffffffffu, s, off);
    if ((tid & 31) == 0) red1[tid >> 5] = s;
    __syncthreads();
    float tot = 0.0f;
#pragma unroll
    for (int k = 0; k < 8; k++) tot += red1[k];
    float mean = tot * (1.0f / 1024.0f);

    float d0 = v.x - mean, d1 = v.y - mean, d2 = v.z - mean, d3 = v.w - mean;
    float sq = d0 * d0 + d1 * d1 + d2 * d2 + d3 * d3;
#pragma unroll
    for (int off = 16; off > 0; off >>= 1) sq += __shfl_xor_sync(0xffffffffu, sq, off);
    if ((tid & 31) == 0) red2[tid >> 5] = sq;
    __syncthreads();
    float vtot = 0.0f;
#pragma unroll
    for (int k = 0; k < 8; k++) vtot += red2[k];
    float rstd = rsqrtf(vtot * (1.0f / 1024.0f) + 1e-6f);

    float4 g4 = *(const float4*)(gamma + tid * 4);
    float4 b4 = *(const float4*)(beta  + tid * 4);
    float4 o4 = make_float4(d0 * rstd * g4.x + b4.x,
                            d1 * rstd * g4.y + b4.y,
                            d2 * rstd * g4.z + b4.z,
                            d3 * rstd * g4.w + b4.w);
    *(float4*)(out + base) = o4;

    if (hi != nullptr) {
        uint2 hw;
        hw.x = hi_pack(o4.x, o4.y);
        hw.y = hi_pack(o4.z, o4.w);
        *(uint2*)(hi + base) = hw;
    }
}

// ============================ host launch ====================================
extern "C" void kernel_launch(void* const* d_in, const int* in_sizes, int n_in,
                              void* d_out, int out_size)
{
    (void)in_sizes; (void)n_in; (void)out_size;
    const float* x  = (const float*)d_in[0];
    const float* y  = (const float*)d_in[1];
    const float* Wq = (const float*)d_in[2];
    const float* bq = (const float*)d_in[3];
    const float* Wk = (const float*)d_in[4];
    const float* bk = (const float*)d_in[5];
    const float* Wv = (const float*)d_in[6];
    const float* bv = (const float*)d_in[7];
    const float* Wf = (const float*)d_in[8];
    const float* bf = (const float*)d_in[9];
    const float* g1 = (const float*)d_in[10];
    const float* b1 = (const float*)d_in[11];
    const float* g2 = (const float*)d_in[12];
    const float* b2 = (const float*)d_in[13];
    float* out = (float*)d_out;

    float *pao, *ph1, *pt;
    cudaGetSymbolAddress((void**)&pao, g_ao);
    cudaGetSymbolAddress((void**)&ph1, g_h1);
    cudaGetSymbolAddress((void**)&pt,  g_t);

    void *paxh, *payh, *pwth, *pqh, *pkh, *pvh;
    cudaGetSymbolAddress(&paxh, g_axh);
    cudaGetSymbolAddress(&payh, g_ayh);
    cudaGetSymbolAddress(&pwth, g_wth);
    cudaGetSymbolAddress(&pqh, g_qh);
    cudaGetSymbolAddress(&pkh, g_kh);
    cudaGetSymbolAddress(&pvh, g_vh);

    __half* axh = (__half*)paxh;
    __half* ayh = (__half*)payh;
    __half* wth = (__half*)pwth;
    __half* qh = (__half*)pqh;
    __half* kh = (__half*)pkh;
    __half* vh = (__half*)pvh;
    const size_t WSZ = (size_t)DDIM * DDIM;

    cudaFuncSetAttribute(gemm_mma<1>, cudaFuncAttributeMaxDynamicSharedMemorySize, GSMEM);
    cudaFuncSetAttribute(gemm_mma<3>, cudaFuncAttributeMaxDynamicSharedMemorySize, GSMEM);
    cudaFuncSetAttribute(attn_mma, cudaFuncAttributeMaxDynamicSharedMemorySize, ASMEM);

    dim3 sgrid((MROWS * DDIM) / 4 / 256, 1, 2);        // (8192,1,2)
    dim3 tgrid(32, 32, 4), tblk(256);
    dim3 ggrid(DDIM / 128, MROWS / 128);                // (8, 64) = 512 CTAs

    // prep: fp16 converts + weight transposes (merged launches)
    conv2_kernel<<<sgrid, 256>>>(x, y, axh, ayh);
    tsplit4_kernel<<<tgrid, tblk>>>(Wq, Wk, Wv, Wf, wth);

    // projections -> fp16
    gemm_mma<3><<<ggrid, 256, GSMEM>>>(axh, wth + 0 * WSZ, bq, nullptr, nullptr, qh);
    gemm_mma<3><<<ggrid, 256, GSMEM>>>(ayh, wth + 1 * WSZ, bk, nullptr, nullptr, kh);
    gemm_mma<3><<<ggrid, 256, GSMEM>>>(ayh, wth + 2 * WSZ, bv, nullptr, nullptr, vh);

    // attention (fp16 1-pass)
    attn_mma<<<dim3(NSEQ / 128, BB * NH), 256, ASMEM>>>(qh, kh, vh, pao);

    // LN1(x + attn) -> fp32 h1 AND fp16 (reuses axh)
    ln_kernel<<<MROWS, 256>>>(x, pao, g1, b1, ph1, axh);

    // FF: t = relu(h1 @ Wf + bf) + h1
    gemm_mma<1><<<ggrid, 256, GSMEM>>>(axh, wth + 3 * WSZ, bf, ph1, pt, nullptr);

    // LN2
    ln_kernel<<<MROWS, 256>>>(pt, nullptr, g2, b2, out, nullptr);
}

// round 14
// speedup vs baseline: 27.2258x; 1.0662x over previous
#include <cuda_runtime.h>
#include <cuda_fp16.h>
#include <math.h>
#include <stdint.h>

// Problem constants
#define BB    8
#define NSEQ  1024
#define DDIM  1024
#define NH    16
#define DHEAD 64
#define MROWS (BB * NSEQ)   // 8192

// ============================ PTX helpers ====================================
__device__ __forceinline__ uint32_t smem_u32(const void* p) {
    uint32_t a;
    asm("{ .reg .u64 t; cvta.to.shared.u64 t, %1; cvt.u32.u64 %0, t; }" : "=r"(a) : "l"(p));
    return a;
}
__device__ __forceinline__ void cp16(uint32_t d, const void* s) {
    asm volatile("cp.async.cg.shared.global [%0], [%1], 16;" :: "r"(d), "l"(s) : "memory");
}
#define CP_COMMIT() asm volatile("cp.async.commit_group;" ::: "memory")
#define CP_WAIT(n)  asm volatile("cp.async.wait_group %0;" :: "n"(n) : "memory")

__device__ __forceinline__ void ldsm4(uint32_t* r, uint32_t a) {
    asm volatile("ldmatrix.sync.aligned.m8n8.x4.shared.b16 {%0,%1,%2,%3}, [%4];"
        : "=r"(r[0]), "=r"(r[1]), "=r"(r[2]), "=r"(r[3]) : "r"(a));
}
__device__ __forceinline__ void ldsm4t(uint32_t* r, uint32_t a) {
    asm volatile("ldmatrix.sync.aligned.m8n8.x4.trans.shared.b16 {%0,%1,%2,%3}, [%4];"
        : "=r"(r[0]), "=r"(r[1]), "=r"(r[2]), "=r"(r[3]) : "r"(a));
}
// fp16 in, fp32 accumulate
__device__ __forceinline__ void mma16816(float* c, const uint32_t* a, const uint32_t* b) {
    asm volatile("mma.sync.aligned.m16n8k16.row.col.f32.f16.f16.f32 "
        "{%0,%1,%2,%3}, {%4,%5,%6,%7}, {%8,%9}, {%0,%1,%2,%3};"
        : "+f"(c[0]), "+f"(c[1]), "+f"(c[2]), "+f"(c[3])
        : "r"(a[0]), "r"(a[1]), "r"(a[2]), "r"(a[3]), "r"(b[0]), "r"(b[1]));
}
__device__ __forceinline__ uint32_t hi_pack(float x, float y) {
    __half2 hv = __halves2half2(__float2half_rn(x), __float2half_rn(y));
    return *(uint32_t*)&hv;
}

// ============================ scratch buffers ================================
__device__ float g_ao[(size_t)MROWS * DDIM];
__device__ float g_h1[(size_t)MROWS * DDIM];
__device__ float g_t [(size_t)MROWS * DDIM];

__device__ __align__(1024) __half g_axh[(size_t)MROWS * DDIM];   // x / h1 fp16
__device__ __align__(1024) __half g_ayh[(size_t)MROWS * DDIM];   // y fp16
__device__ __align__(1024) __half g_wth[4][(size_t)DDIM * DDIM]; // weights^T fp16
__device__ __align__(1024) __half g_qh[(size_t)MROWS * DDIM];
__device__ __align__(1024) __half g_kh[(size_t)MROWS * DDIM];
__device__ __align__(1024) __half g_vh[(size_t)MROWS * DDIM];

// ============================ convert / transpose (merged launches) ==========
__global__ __launch_bounds__(256)
void conv2_kernel(const float* __restrict__ in0, const float* __restrict__ in1,
                  __half* __restrict__ o0, __half* __restrict__ o1)
{
    const float* in = blockIdx.z ? in1 : in0;
    __half* o = blockIdx.z ? o1 : o0;
    int i = blockIdx.x * 256 + threadIdx.x;
    float4 v = ((const float4*)in)[i];
    uint2 hw;
    hw.x = hi_pack(v.x, v.y);
    hw.y = hi_pack(v.z, v.w);
    ((uint2*)o)[i] = hw;
}

__global__ __launch_bounds__(256)
void tsplit4_kernel(const float* __restrict__ W0, const float* __restrict__ W1,
                    const float* __restrict__ W2, const float* __restrict__ W3,
                    __half* __restrict__ thb)
{
    const int w = blockIdx.z;
    const float* W = (w == 0) ? W0 : (w == 1) ? W1 : (w == 2) ? W2 : W3;
    __half* th = thb + (size_t)w * DDIM * DDIM;

    __shared__ float t[32][33];
    const int tx = threadIdx.x & 31;
    const int ty = threadIdx.x >> 5;
    const int kb = blockIdx.y * 32;
    const int nb = blockIdx.x * 32;
#pragma unroll
    for (int i = 0; i < 4; i++) {
        int kk = ty + i * 8;
        t[kk][tx] = W[(size_t)(kb + kk) * DDIM + nb + tx];
    }
    __syncthreads();
#pragma unroll
    for (int i = 0; i < 4; i++) {
        int nn = ty + i * 8;
        th[(size_t)(nb + nn) * DDIM + kb + tx] = __float2half_rn(t[tx][nn]);
    }
}

// ============================ HMMA GEMM (fp16 1-pass, fp32 acc) ==============
// BM=128, BN=128, BK=64, 256 threads, warp tile 64x32, 2 stages, 2 CTAs/SM.
// QKV=true: blockIdx.z selects {x@Wq->Q, y@Wk->K, y@Wv->V}, fp16 out.
// QKV=false: C = relu(A@W+b)+res (fp32) — the FF GEMM.
#define G_SST   144                      // smem row stride bytes (72 halves)
#define G_TILE  (128 * G_SST)            // 18432
#define G_STAGE (2 * G_TILE)             // 36864 : A, B
#define GSMEM   (2 * G_STAGE)            // 73728

template <bool QKV>
__global__ __launch_bounds__(256, 2)
void gemm_mma(const __half* __restrict__ Ax, const __half* __restrict__ Ay,
              const __half* __restrict__ Wt,
              const float* __restrict__ b0, const float* __restrict__ b1_,
              const float* __restrict__ b2_,
              const float* __restrict__ res, float* __restrict__ C,
              __half* __restrict__ O0, __half* __restrict__ O1,
              __half* __restrict__ O2)
{
    extern __shared__ __align__(128) char gsm[];
    const uint32_t sb = smem_u32(gsm);
    const int tid = threadIdx.x, lid = tid & 31, wid = tid >> 5;
    const int wm = (wid & 1) * 64, wn = (wid >> 1) * 32;
    const int bm = blockIdx.y * 128, bn = blockIdx.x * 128;
    const int z  = QKV ? blockIdx.z : 0;

    const __half* A_ = QKV ? (z == 0 ? Ax : Ay) : Ax;
    const __half* B_ = Wt + (size_t)z * DDIM * DDIM;
    const float* bias = QKV ? (z == 0 ? b0 : (z == 1 ? b1_ : b2_)) : b0;
    __half* Ch = QKV ? (z == 0 ? O0 : (z == 1 ? O1 : O2)) : nullptr;

    const uint32_t aoff = (uint32_t)(wm + (lid & 15)) * G_SST + (((lid >> 4) & 1) * 16);
    const uint32_t boff = (uint32_t)(wn + ((lid >> 4) & 1) * 8 + (lid & 7)) * G_SST
                        + (((lid >> 3) & 1) * 16);

    float acc[4][4][4];
#pragma unroll
    for (int i = 0; i < 4; i++)
#pragma unroll
        for (int j = 0; j < 4; j++)
#pragma unroll
            for (int e = 0; e < 4; e++) acc[i][j][e] = 0.0f;

    auto LOAD = [&](int stg, int k0) {
        const uint32_t s = sb + (uint32_t)stg * G_STAGE;
#pragma unroll
        for (int t = 0; t < 4; t++) {
            int idx = tid + t * 256;
            int r = idx >> 3, sg = idx & 7;
            uint32_t so = (uint32_t)r * G_SST + sg * 16;
            size_t goA = (size_t)(bm + r) * DDIM + k0 + sg * 8;
            size_t goB = (size_t)(bn + r) * DDIM + k0 + sg * 8;
            cp16(s + so,          A_ + goA);
            cp16(s + G_TILE + so, B_ + goB);
        }
    };

    LOAD(0, 0);
    CP_COMMIT();

    for (int c = 0; c < 16; c++) {
        if (c + 1 < 16) { LOAD((c + 1) & 1, (c + 1) * 64); CP_COMMIT(); CP_WAIT(1); }
        else            { CP_WAIT(0); }
        __syncthreads();
        const uint32_t st = sb + (uint32_t)(c & 1) * G_STAGE;

#pragma unroll
        for (int s = 0; s < 4; s++) {
            const uint32_t ks = s * 32;
            uint32_t AH[4][4], B0[4], B1[4];
#pragma unroll
            for (int i = 0; i < 4; i++)
                ldsm4(AH[i], st + aoff + (uint32_t)(i * 16) * G_SST + ks);
            ldsm4(B0, st + G_TILE + boff + ks);
            ldsm4(B1, st + G_TILE + boff + (uint32_t)(16 * G_SST) + ks);
#pragma unroll
            for (int i = 0; i < 4; i++) {
                mma16816(acc[i][0], AH[i], &B0[0]);
                mma16816(acc[i][1], AH[i], &B0[2]);
                mma16816(acc[i][2], AH[i], &B1[0]);
                mma16816(acc[i][3], AH[i], &B1[2]);
            }
        }
        __syncthreads();
    }

    // epilogue
    const int gr = lid >> 2, gc = (lid & 3) * 2;
#pragma unroll
    for (int i = 0; i < 4; i++) {
        const int r0 = bm + wm + i * 16 + gr;
        const int r1 = r0 + 8;
#pragma unroll
        for (int j = 0; j < 4; j++) {
            const int col = bn + wn + j * 8 + gc;
            const float bx = bias[col], by = bias[col + 1];
            float v0 = acc[i][j][0] + bx, v1 = acc[i][j][1] + by;
            float v2 = acc[i][j][2] + bx, v3 = acc[i][j][3] + by;
            if (QKV) {
                *(uint32_t*)(Ch + (size_t)r0 * DDIM + col) = hi_pack(v0, v1);
                *(uint32_t*)(Ch + (size_t)r1 * DDIM + col) = hi_pack(v2, v3);
            } else {
                const float* rp0 = res + (size_t)r0 * DDIM + col;
                const float* rp1 = res + (size_t)r1 * DDIM + col;
                v0 = fmaxf(v0, 0.0f) + rp0[0];
                v1 = fmaxf(v1, 0.0f) + rp0[1];
                v2 = fmaxf(v2, 0.0f) + rp1[0];
                v3 = fmaxf(v3, 0.0f) + rp1[1];
                *(float2*)(C + (size_t)r0 * DDIM + col) = make_float2(v0, v1);
                *(float2*)(C + (size_t)r1 * DDIM + col) = make_float2(v2, v3);
            }
        }
    }
}

// ============================ HMMA flash attention (fp16 1-pass) =============
// CTA = 128 q-rows of one (b,h), 256 threads (8 warps x 16 rows).
// KV chunks of 64 (sacc 32 regs) -> 2 CTAs/SM. 2-stage pipeline, 16 chunks.
#define AST_B    144
#define AQT_B    (128 * AST_B)             // Q tile: 18432
#define AKV_B    (64 * AST_B)              // K or V tile: 9216
#define ASMEM    (AQT_B + 4 * AKV_B)       // 55296

__global__ __launch_bounds__(256, 2)
void attn_mma(const __half* __restrict__ Q_g, const __half* __restrict__ K_g,
              const __half* __restrict__ V_g, float* __restrict__ O)
{
    extern __shared__ __align__(128) char asm_[];
    const uint32_t sb = smem_u32(asm_);
    const int tid = threadIdx.x, lid = tid & 31, wid = tid >> 5;
    const int bh = blockIdx.y, b = bh >> 4, h = bh & 15;
    const int q0 = blockIdx.x * 128;

    const size_t qbase = (size_t)(b * NSEQ + q0) * DDIM + h * DHEAD;
    const size_t kbase = (size_t)(b * NSEQ) * DDIM + h * DHEAD;

    const uint32_t sQ  = sb;
    const uint32_t kv0 = sb + AQT_B;
    const uint32_t aoff = (uint32_t)(16 * wid + (lid & 15)) * AST_B + ((lid >> 4) & 1) * 16;
    const uint32_t boff = (uint32_t)(((lid >> 4) & 1) * 8 + (lid & 7)) * AST_B
                        + ((lid >> 3) & 1) * 16;
    const uint32_t voff = (uint32_t)(lid & 15) * AST_B + ((lid >> 4) & 1) * 16;

    auto loadKV = [&](int kt, int st) {
        const uint32_t base = kv0 + (uint32_t)st * (2 * AKV_B);
        const size_t gk = kbase + (size_t)(kt * 64) * DDIM;
        for (int i = tid; i < 512; i += 256) {
            int r = i >> 3, sg = i & 7;
            uint32_t so = (uint32_t)r * AST_B + sg * 16;
            size_t go = gk + (size_t)r * DDIM + sg * 8;
            cp16(base + so,         K_g + go);
            cp16(base + AKV_B + so, V_g + go);
        }
    };

    for (int i = tid; i < 1024; i += 256) {
        int r = i >> 3, sg = i & 7;
        uint32_t so = (uint32_t)r * AST_B + sg * 16;
        cp16(sQ + so, Q_g + qbase + (size_t)r * DDIM + sg * 8);
    }
    loadKV(0, 0);
    CP_COMMIT();
    loadKV(1, 1);
    CP_COMMIT();
    CP_WAIT(1);
    __syncthreads();

    float m0 = -1e30f, m1 = -1e30f, l0v = 0.0f, l1v = 0.0f;
    float ov[8][4];
#pragma unroll
    for (int j = 0; j < 8; j++)
#pragma unroll
        for (int e = 0; e < 4; e++) ov[j][e] = 0.0f;

    for (int kt = 0; kt < 16; kt++) {
        const uint32_t kvb = kv0 + (uint32_t)(kt & 1) * (2 * AKV_B);

        float sacc[8][4];
#pragma unroll
        for (int t = 0; t < 8; t++)
#pragma unroll
            for (int e = 0; e < 4; e++) sacc[t][e] = 0.0f;

#pragma unroll
        for (int kk = 0; kk < 4; kk++) {
            uint32_t QF[4];
            ldsm4(QF, sQ + aoff + kk * 32);
#pragma unroll
            for (int n = 0; n < 4; n++) {
                uint32_t KB[4];
                ldsm4(KB, kvb + boff + (uint32_t)n * (16 * AST_B) + kk * 32);
                mma16816(sacc[2 * n],     QF, &KB[0]);
                mma16816(sacc[2 * n + 1], QF, &KB[2]);
            }
        }

        const float scale = 0.03125f;
        float mx0 = -1e30f, mx1 = -1e30f;
#pragma unroll
        for (int t = 0; t < 8; t++) {
            sacc[t][0] *= scale; sacc[t][1] *= scale;
            sacc[t][2] *= scale; sacc[t][3] *= scale;
            mx0 = fmaxf(mx0, fmaxf(sacc[t][0], sacc[t][1]));
            mx1 = fmaxf(mx1, fmaxf(sacc[t][2], sacc[t][3]));
        }
        mx0 = fmaxf(mx0, __shfl_xor_sync(0xffffffffu, mx0, 1));
        mx0 = fmaxf(mx0, __shfl_xor_sync(0xffffffffu, mx0, 2));
        mx1 = fmaxf(mx1, __shfl_xor_sync(0xffffffffu, mx1, 1));
        mx1 = fmaxf(mx1, __shfl_xor_sync(0xffffffffu, mx1, 2));
        const float mn0 = fmaxf(m0, mx0), mn1 = fmaxf(m1, mx1);
        const float a0 = __expf(m0 - mn0), a1 = __expf(m1 - mn1);
        float rs0 = 0.0f, rs1 = 0.0f;
#pragma unroll
        for (int t = 0; t < 8; t++) {
            float e0 = __expf(sacc[t][0] - mn0);
            float e1 = __expf(sacc[t][1] - mn0);
            float e2 = __expf(sacc[t][2] - mn1);
            float e3 = __expf(sacc[t][3] - mn1);
            sacc[t][0] = e0; sacc[t][1] = e1; sacc[t][2] = e2; sacc[t][3] = e3;
            rs0 += e0 + e1; rs1 += e2 + e3;
        }
        rs0 += __shfl_xor_sync(0xffffffffu, rs0, 1);
        rs0 += __shfl_xor_sync(0xffffffffu, rs0, 2);
        rs1 += __shfl_xor_sync(0xffffffffu, rs1, 1);
        rs1 += __shfl_xor_sync(0xffffffffu, rs1, 2);
        l0v = l0v * a0 + rs0;
        l1v = l1v * a1 + rs1;
        m0 = mn0; m1 = mn1;
#pragma unroll
        for (int j = 0; j < 8; j++) {
            ov[j][0] *= a0; ov[j][1] *= a0;
            ov[j][2] *= a1; ov[j][3] *= a1;
        }

        const uint32_t sVh = kvb + AKV_B;
#pragma unroll
        for (int t = 0; t < 4; t++) {
            uint32_t aP[4];
            aP[0] = hi_pack(sacc[2 * t][0],     sacc[2 * t][1]);
            aP[1] = hi_pack(sacc[2 * t][2],     sacc[2 * t][3]);
            aP[2] = hi_pack(sacc[2 * t + 1][0], sacc[2 * t + 1][1]);
            aP[3] = hi_pack(sacc[2 * t + 1][2], sacc[2 * t + 1][3]);
#pragma unroll
            for (int nv = 0; nv < 4; nv++) {
                uint32_t VB[4];
                ldsm4t(VB, sVh + voff + (uint32_t)t * (16 * AST_B) + nv * 32);
                mma16816(ov[2 * nv],     aP, &VB[0]);
                mma16816(ov[2 * nv + 1], aP, &VB[2]);
            }
        }

        __syncthreads();
        if (kt + 2 < 16) {
            loadKV(kt + 2, kt & 1);
            CP_COMMIT();
            CP_WAIT(1);
            __syncthreads();
        } else if (kt + 1 < 16) {
            CP_WAIT(0);
            __syncthreads();
        }
    }

    const float inv0 = 1.0f / l0v, inv1 = 1.0f / l1v;
    const int gr = lid >> 2, gc = (lid & 3) * 2;
    float* op0 = O + (size_t)(b * NSEQ + q0 + 16 * wid + gr) * DDIM + h * DHEAD;
    float* op1 = op0 + 8 * DDIM;
#pragma unroll
    for (int j = 0; j < 8; j++) {
        *(float2*)(op0 + j * 8 + gc) = make_float2(ov[j][0] * inv0, ov[j][1] * inv0);
        *(float2*)(op1 + j * 8 + gc) = make_float2(ov[j][2] * inv1, ov[j][3] * inv1);
    }
}

// ============================ LayerNorm (+ optional fp16 out) ================
__global__ __launch_bounds__(256)
void ln_kernel(const float* __restrict__ A, const float* __restrict__ R,
               const float* __restrict__ gamma, const float* __restrict__ beta,
               float* __restrict__ out, __half* __restrict__ hi)
{
    const int row = blockIdx.x;
    const int tid = threadIdx.x;
    const size_t base = (size_t)row * DDIM + tid * 4;

    float4 v = *(const float4*)(A + base);
    if (R != nullptr) {
        float4 r = *(const float4*)(R + base);
        v.x += r.x; v.y += r.y; v.z += r.z; v.w += r.w;
    }

    __shared__ float red1[8];
    __shared__ float red2[8];

    float s = v.x + v.y + v.z + v.w;
#pragma unroll
    for (int off = 16; off > 0; off >>= 1) s += __shfl_xor_sync(0xffffffffu, s, off);
    if ((tid & 31) == 0) red1[tid >> 5] = s;
    __syncthreads();
    float tot = 0.0f;
#pragma unroll
    for (int k = 0; k < 8; k++) tot += red1[k];
    float mean = tot * (1.0f / 1024.0f);

    float d0 = v.x - mean, d1 = v.y - mean, d2 = v.z - mean, d3 = v.w - mean;
    float sq = d0 * d0 + d1 * d1 + d2 * d2 + d3 * d3;
#pragma unroll
    for (int off = 16; off > 0; off >>= 1) sq += __shfl_xor_sync(0xffffffffu, sq, off);
    if ((tid & 31) == 0) red2[tid >> 5] = sq;
    __syncthreads();
    float vtot = 0.0f;
#pragma unroll
    for (int k = 0; k < 8; k++) vtot += red2[k];
    float rstd = rsqrtf(vtot * (1.0f / 1024.0f) + 1e-6f);

    float4 g4 = *(const float4*)(gamma + tid * 4);
    float4 b4 = *(const float4*)(beta  + tid * 4);
    float4 o4 = make_float4(d0 * rstd * g4.x + b4.x,
                            d1 * rstd * g4.y + b4.y,
                            d2 * rstd * g4.z + b4.z,
                            d3 * rstd * g4.w + b4.w);
    *(float4*)(out + base) = o4;

    if (hi != nullptr) {
        uint2 hw;
        hw.x = hi_pack(o4.x, o4.y);
        hw.y = hi_pack(o4.z, o4.w);
        *(uint2*)(hi + base) = hw;
    }
}

// ============================ host launch ====================================
extern "C" void kernel_launch(void* const* d_in, const int* in_sizes, int n_in,
                              void* d_out, int out_size)
{
    (void)in_sizes; (void)n_in; (void)out_size;
    const float* x  = (const float*)d_in[0];
    const float* y  = (const float*)d_in[1];
    const float* Wq = (const float*)d_in[2];
    const float* bq = (const float*)d_in[3];
    const float* Wk = (const float*)d_in[4];
    const float* bk = (const float*)d_in[5];
    const float* Wv = (const float*)d_in[6];
    const float* bv = (const float*)d_in[7];
    const float* Wf = (const float*)d_in[8];
    const float* bf = (const float*)d_in[9];
    const float* g1 = (const float*)d_in[10];
    const float* b1 = (const float*)d_in[11];
    const float* g2 = (const float*)d_in[12];
    const float* b2 = (const float*)d_in[13];
    float* out = (float*)d_out;

    float *pao, *ph1, *pt;
    cudaGetSymbolAddress((void**)&pao, g_ao);
    cudaGetSymbolAddress((void**)&ph1, g_h1);
    cudaGetSymbolAddress((void**)&pt,  g_t);

    void *paxh, *payh, *pwth, *pqh, *pkh, *pvh;
    cudaGetSymbolAddress(&paxh, g_axh);
    cudaGetSymbolAddress(&payh, g_ayh);
    cudaGetSymbolAddress(&pwth, g_wth);
    cudaGetSymbolAddress(&pqh, g_qh);
    cudaGetSymbolAddress(&pkh, g_kh);
    cudaGetSymbolAddress(&pvh, g_vh);

    __half* axh = (__half*)paxh;
    __half* ayh = (__half*)payh;
    __half* wth = (__half*)pwth;
    __half* qh = (__half*)pqh;
    __half* kh = (__half*)pkh;
    __half* vh = (__half*)pvh;
    const size_t WSZ = (size_t)DDIM * DDIM;

    cudaFuncSetAttribute(gemm_mma<true>,  cudaFuncAttributeMaxDynamicSharedMemorySize, GSMEM);
    cudaFuncSetAttribute(gemm_mma<false>, cudaFuncAttributeMaxDynamicSharedMemorySize, GSMEM);
    cudaFuncSetAttribute(attn_mma, cudaFuncAttributeMaxDynamicSharedMemorySize, ASMEM);

    dim3 sgrid((MROWS * DDIM) / 4 / 256, 1, 2);        // (8192,1,2)
    dim3 tgrid(32, 32, 4), tblk(256);
    dim3 qkvgrid(DDIM / 128, MROWS / 128, 3);           // (8, 64, 3) = 1536 CTAs
    dim3 ffgrid(DDIM / 128, MROWS / 128, 1);            // (8, 64)

    // prep: fp16 converts + weight transposes (merged launches)
    conv2_kernel<<<sgrid, 256>>>(x, y, axh, ayh);
    tsplit4_kernel<<<tgrid, tblk>>>(Wq, Wk, Wv, Wf, wth);

    // fused QKV projections -> fp16 (one launch, packed waves)
    gemm_mma<true><<<qkvgrid, 256, GSMEM>>>(axh, ayh, wth, bq, bk, bv,
                                            nullptr, nullptr, qh, kh, vh);

    // attention (fp16 1-pass, KV chunk 64, 2 CTAs/SM)
    attn_mma<<<dim3(NSEQ / 128, BB * NH), 256, ASMEM>>>(qh, kh, vh, pao);

    // LN1(x + attn) -> fp32 h1 AND fp16 (reuses axh)
    ln_kernel<<<MROWS, 256>>>(x, pao, g1, b1, ph1, axh);

    // FF: t = relu(h1 @ Wf + bf) + h1
    gemm_mma<false><<<ffgrid, 256, GSMEM>>>(axh, nullptr, wth + 3 * WSZ, bf, nullptr,
                                            nullptr, ph1, pt, nullptr, nullptr, nullptr);

    // LN2
    ln_kernel<<<MROWS, 256>>>(pt, nullptr, g2, b2, out, nullptr);
}